// round 7
// baseline (speedup 1.0000x reference)
#include <cuda_runtime.h>
#include <cuda_bf16.h>
#include <math.h>
#include <stdint.h>

#define BB   4096
#define FF   24
#define VV   1000
#define DD   32
#define FD   768
#define COMB 1536
#define H0N  1024
#define H1N  512
#define RED  8
#define EPSV 1e-5f

// ---------------- device scratch ----------------
__device__ __align__(16) float g_E2r[2 * BB * FD];   // tf32-rounded embeddings [e ; A*e]
__device__ __align__(16) float g_WTn[FD * FD];       // bilinear W as [n=ik][k=jl], diag zero, tf32
__device__ __align__(16) float g_comb[BB * COMB];    // tf32-rounded
__device__ __align__(16) float g_h0[BB * H0N];
__device__ __align__(16) float g_h0t[BB * H0N];      // relu(bn(h0)) tf32-rounded
__device__ __align__(16) float g_h1[BB * H1N];
__device__ __align__(16) float g_w0t[H0N * COMB];    // w0^T tf32 [n][k]
__device__ __align__(16) float g_w1t[H1N * H0N];     // w1^T tf32
__device__ float g_lin[BB];
__device__ float g_scale0[H0N], g_shift0[H0N];
__device__ float g_scale1[H1N], g_shift1[H1N];

#define CVT_TF32(u, f) asm("cvt.rna.tf32.f32 %0, %1;" : "=r"(u) : "f"(f))
__device__ __forceinline__ float tf32r(float f) {
    unsigned u; CVT_TF32(u, f); return __uint_as_float(u);
}

// ---------------- K0: W -> [ik][jl], diag zeroed, tf32 ---------------------
__global__ void transposeW_kernel(const float* __restrict__ W, float* __restrict__ WTn) {
    int o = blockIdx.x * 256 + threadIdx.x;        // o = ik*768 + jl
    int jl = o % FD, ik = o / FD;
    int i = ik >> 5, k = ik & 31, j = jl >> 5, l = jl & 31;
    float v = (i == j) ? 0.f : W[(((i * FF + j) * DD + k) * DD) + l];
    WTn[o] = tf32r(v);
}

// ---------------- weight transpose + tf32 round: [K][N] -> [N][K] ----------
__global__ void transpose_cvt_kernel(const float* __restrict__ src, float* __restrict__ dst,
                                     int K, int N) {
    __shared__ float tile[32][33];
    int k0 = blockIdx.x * 32, n0 = blockIdx.y * 32;
    int tx = threadIdx.x, ty = threadIdx.y;        // 32 x 8
    #pragma unroll
    for (int j = 0; j < 4; j++)
        tile[ty + j * 8][tx] = src[(long)(k0 + ty + j * 8) * N + n0 + tx];
    __syncthreads();
    #pragma unroll
    for (int j = 0; j < 4; j++)
        dst[(long)(n0 + ty + j * 8) * K + k0 + tx] = tf32r(tile[tx][ty + j * 8]);
}

// ---------------- K1: gather + linear + SENet -----------------------------
__global__ void gather_se_kernel(const int* __restrict__ x,
                                 const float* __restrict__ emb,
                                 const float* __restrict__ lint,
                                 const float* __restrict__ sw1,
                                 const float* __restrict__ sw2,
                                 float* __restrict__ E2r,
                                 float* __restrict__ linout) {
    int b = blockIdx.x;
    int t = threadIdx.x;
    __shared__ int   xs[FF];
    __shared__ float es[FD];
    __shared__ float Zs[FF], hid[RED], As[FF], linp[FF];

    if (t < FF) xs[t] = x[b * FF + t];
    __syncthreads();

    #pragma unroll
    for (int r = 0; r < 3; r++) {
        int ik = t + r * 256;
        int f = ik >> 5, d = ik & 31;
        es[ik] = emb[((long)f * VV + xs[f]) * DD + d];
    }
    if (t < FF) linp[t] = lint[(long)t * VV + xs[t]];
    __syncthreads();

    int w = t >> 5, lane = t & 31;
    #pragma unroll
    for (int ff = 0; ff < 3; ff++) {
        int f = w * 3 + ff;
        float v = es[f * 32 + lane];
        #pragma unroll
        for (int o = 16; o > 0; o >>= 1) v += __shfl_xor_sync(0xffffffffu, v, o);
        if (lane == 0) Zs[f] = v * (1.f / 32.f);
    }
    __syncthreads();
    if (t < RED) {
        float s = 0.f;
        #pragma unroll
        for (int f = 0; f < FF; f++) s += Zs[f] * sw1[t * FF + f];
        hid[t] = fmaxf(s, 0.f);
    }
    __syncthreads();
    if (t < FF) {
        float s = 0.f;
        #pragma unroll
        for (int r = 0; r < RED; r++) s += hid[r] * sw2[t * RED + r];
        As[t] = 1.f / (1.f + expf(-s));
    }
    if (t == 0) {
        float s = 0.f;
        #pragma unroll
        for (int f = 0; f < FF; f++) s += linp[f];
        linout[b] = s;
    }
    __syncthreads();

    #pragma unroll
    for (int r = 0; r < 3; r++) {
        int ik = t + r * 256;
        int f = ik >> 5;
        float e = es[ik];
        E2r[(long)b * FD + ik] = tf32r(e);
        E2r[(long)(BB + b) * FD + ik] = tf32r(As[f] * e);
    }
}

// ---------------- tf32 tensor-core GEMM v4 ---------------------------------
// 128 thr = 4 warps (2x2); block 128x128; warp 64x64; ktile 16.
// Smem per operand: [128 rows][24 words]; row holds 16 k-words as interleaved
// pairs: chunk c(<4)={k=c,k=c+4}, c(>=4)={k=c+4,k=c+8}; unit u=c>>1 XOR'd by
// (row>>2)&1. Fragment (ks,quad) = one LDS.64 at base (+8 words for ks=8).
// All operands pre-rounded tf32 in global; B given as [N][K].
template <bool BIAS, bool COMBINE>
__global__ void __launch_bounds__(128, 2)
gemm4_kernel(const float* __restrict__ A, const float* __restrict__ Bt,
             float* __restrict__ C, int M, int N, int K,
             const float* __restrict__ bias, const float* __restrict__ E2) {
    __shared__ __align__(16) unsigned Asm[2][128 * 24];
    __shared__ __align__(16) unsigned Bsm[2][128 * 24];
    int t = threadIdx.x;
    int m0 = blockIdx.x * 128, n0 = blockIdx.y * 128;
    int wid = t >> 5, lane = t & 31;
    int wm = (wid & 1) * 64, wn = (wid >> 1) * 64;
    int r = lane >> 2, quad = lane & 3;

    float acc[4][8][4];
    #pragma unroll
    for (int mi = 0; mi < 4; mi++)
        #pragma unroll
        for (int ni = 0; ni < 8; ni++)
            #pragma unroll
            for (int c = 0; c < 4; c++) acc[mi][ni][c] = 0.f;

    // staging: thread t owns row t of both A and B tiles
    const float* Ap = A + (long)(m0 + t) * K;
    const float* Bp = Bt + (long)(n0 + t) * K;
    int rbs = (t >> 2) & 1;
    int st[4];
    #pragma unroll
    for (int u = 0; u < 4; u++) st[u] = t * 24 + ((u ^ rbs) << 2);

    // fragment base offsets (words); ks=8 -> +8
    int iaf[4][2], ibf[8];
    #pragma unroll
    for (int mi = 0; mi < 4; mi++) {
        int r0 = wm + mi * 16 + r, r1 = r0 + 8;
        iaf[mi][0] = r0 * 24 + (((quad >> 1) ^ ((r0 >> 2) & 1)) << 2) + ((quad & 1) << 1);
        iaf[mi][1] = r1 * 24 + (((quad >> 1) ^ ((r1 >> 2) & 1)) << 2) + ((quad & 1) << 1);
    }
    #pragma unroll
    for (int ni = 0; ni < 8; ni++) {
        int nr = wn + ni * 8 + r;
        ibf[ni] = nr * 24 + (((quad >> 1) ^ ((nr >> 2) & 1)) << 2) + ((quad & 1) << 1);
    }

    float4 ga[4], gb[4];
    #pragma unroll
    for (int j = 0; j < 4; j++) {
        ga[j] = *(const float4*)(Ap + j * 4);
        gb[j] = *(const float4*)(Bp + j * 4);
    }

    // interleave {k,k+4} pairs + tf32-bitcast store (values already rounded)
    #define STAGE(buf)                                                          \
        do {                                                                    \
            _Pragma("unroll")                                                   \
            for (int hh = 0; hh < 2; hh++) {                                    \
                float4 p = ga[hh * 2], q = ga[hh * 2 + 1];                      \
                uint4 u0, u1;                                                   \
                u0.x = __float_as_uint(p.x); u0.y = __float_as_uint(q.x);       \
                u0.z = __float_as_uint(p.y); u0.w = __float_as_uint(q.y);       \
                u1.x = __float_as_uint(p.z); u1.y = __float_as_uint(q.z);       \
                u1.z = __float_as_uint(p.w); u1.w = __float_as_uint(q.w);       \
                *(uint4*)&Asm[buf][st[hh * 2]]     = u0;                        \
                *(uint4*)&Asm[buf][st[hh * 2 + 1]] = u1;                        \
                float4 pb = gb[hh * 2], qb = gb[hh * 2 + 1];                    \
                uint4 v0, v1;                                                   \
                v0.x = __float_as_uint(pb.x); v0.y = __float_as_uint(qb.x);     \
                v0.z = __float_as_uint(pb.y); v0.w = __float_as_uint(qb.y);     \
                v1.x = __float_as_uint(pb.z); v1.y = __float_as_uint(qb.z);     \
                v1.z = __float_as_uint(pb.w); v1.w = __float_as_uint(qb.w);     \
                *(uint4*)&Bsm[buf][st[hh * 2]]     = v0;                        \
                *(uint4*)&Bsm[buf][st[hh * 2 + 1]] = v1;                        \
            }                                                                   \
        } while (0)

    STAGE(0);
    __syncthreads();

    int buf = 0;
    for (int kt = 0; kt < K; kt += 16) {
        bool more = (kt + 16) < K;
        if (more) {
            #pragma unroll
            for (int j = 0; j < 4; j++) {
                ga[j] = *(const float4*)(Ap + kt + 16 + j * 4);
                gb[j] = *(const float4*)(Bp + kt + 16 + j * 4);
            }
        }
        const unsigned* as = Asm[buf];
        const unsigned* bs = Bsm[buf];
        #pragma unroll
        for (int ks = 0; ks < 2; ks++) {
            int x = ks * 8;
            uint2 a[4][2], b[8];
            #pragma unroll
            for (int mi = 0; mi < 4; mi++) {
                a[mi][0] = *(const uint2*)&as[iaf[mi][0] + x];
                a[mi][1] = *(const uint2*)&as[iaf[mi][1] + x];
            }
            #pragma unroll
            for (int ni = 0; ni < 8; ni++) b[ni] = *(const uint2*)&bs[ibf[ni] + x];
            #pragma unroll
            for (int mi = 0; mi < 4; mi++)
                #pragma unroll
                for (int ni = 0; ni < 8; ni++) {
                    asm volatile(
                        "mma.sync.aligned.m16n8k8.row.col.f32.tf32.tf32.f32 "
                        "{%0,%1,%2,%3}, {%4,%5,%6,%7}, {%8,%9}, {%0,%1,%2,%3};"
                        : "+f"(acc[mi][ni][0]), "+f"(acc[mi][ni][1]),
                          "+f"(acc[mi][ni][2]), "+f"(acc[mi][ni][3])
                        : "r"(a[mi][0].x), "r"(a[mi][1].x),
                          "r"(a[mi][0].y), "r"(a[mi][1].y),
                          "r"(b[ni].x), "r"(b[ni].y));
                }
        }
        if (more) STAGE(buf ^ 1);
        __syncthreads();
        buf ^= 1;
    }
    #undef STAGE

    // ---- epilogue ----
    #pragma unroll
    for (int mi = 0; mi < 4; mi++) {
        #pragma unroll
        for (int ni = 0; ni < 8; ni++) {
            int row0 = m0 + wm + mi * 16 + r;
            int row1 = row0 + 8;
            int col  = n0 + wn + ni * 8 + 2 * quad;
            float2 v0 = make_float2(acc[mi][ni][0], acc[mi][ni][1]);
            float2 v1 = make_float2(acc[mi][ni][2], acc[mi][ni][3]);
            if (BIAS) {
                float b0v = bias[col], b1v = bias[col + 1];
                v0.x += b0v; v0.y += b1v;
                v1.x += b0v; v1.y += b1v;
            }
            if (COMBINE) {
                float2 e0 = *(const float2*)&E2[(long)row0 * FD + col];
                float2 e1 = *(const float2*)&E2[(long)row1 * FD + col];
                v0.x = tf32r(v0.x * e0.x); v0.y = tf32r(v0.y * e0.y);
                v1.x = tf32r(v1.x * e1.x); v1.y = tf32r(v1.y * e1.y);
                long br0 = (row0 < BB) ? row0 : (row0 - BB);
                long br1 = (row1 < BB) ? row1 : (row1 - BB);
                int  c0  = (row0 < BB) ? 0 : FD;
                int  c1  = (row1 < BB) ? 0 : FD;
                *(float2*)&C[br0 * (long)COMB + c0 + col] = v0;
                *(float2*)&C[br1 * (long)COMB + c1 + col] = v1;
            } else {
                *(float2*)&C[(long)row0 * N + col] = v0;
                *(float2*)&C[(long)row1 * N + col] = v1;
            }
        }
    }
}

// ---------------- BN stats -> scale/shift ----------------------------------
__global__ void bn_stats_kernel(const float* __restrict__ H, int N,
                                const float* __restrict__ g, const float* __restrict__ be,
                                float* __restrict__ scale, float* __restrict__ shift) {
    int lane = threadIdx.x & 31;
    int ty   = threadIdx.x >> 5;
    int col  = blockIdx.x * 32 + lane;
    float s = 0.f, sq = 0.f;
    for (int r = ty; r < BB; r += 16) {
        float v = H[(long)r * N + col];
        s += v; sq += v * v;
    }
    __shared__ float ss[16][33], sqs[16][33];
    ss[ty][lane] = s; sqs[ty][lane] = sq;
    __syncthreads();
    if (ty == 0) {
        #pragma unroll
        for (int i = 1; i < 16; i++) { s += ss[i][lane]; sq += sqs[i][lane]; }
        float mean = s * (1.f / BB);
        float var  = sq * (1.f / BB) - mean * mean;
        float sc   = g[col] * rsqrtf(var + EPSV);
        scale[col] = sc;
        shift[col] = be[col] - mean * sc;
    }
}

// ---------------- relu(bn(h0)) -> tf32-rounded -----------------------------
__global__ void bnrelu_kernel(const float* __restrict__ H,
                              const float* __restrict__ scale,
                              const float* __restrict__ shift,
                              float* __restrict__ Ht) {
    int i = (blockIdx.x * 256 + threadIdx.x) * 4;
    int col = i & (H0N - 1);
    float4 v = *(const float4*)&H[i];
    v.x = tf32r(fmaxf(0.f, v.x * scale[col + 0] + shift[col + 0]));
    v.y = tf32r(fmaxf(0.f, v.y * scale[col + 1] + shift[col + 1]));
    v.z = tf32r(fmaxf(0.f, v.z * scale[col + 2] + shift[col + 2]));
    v.w = tf32r(fmaxf(0.f, v.w * scale[col + 3] + shift[col + 3]));
    *(float4*)&Ht[i] = v;
}

// ---------------- final ----------------------------------------------------
__global__ void final_kernel(const float* __restrict__ H1,
                             const float* __restrict__ scale, const float* __restrict__ shift,
                             const float* __restrict__ w2, const float* __restrict__ b2,
                             const float* __restrict__ lin, const float* __restrict__ bias0,
                             float* __restrict__ out) {
    int warp = threadIdx.x >> 5, lane = threadIdx.x & 31;
    int row = blockIdx.x * 8 + warp;
    float acc = 0.f;
    #pragma unroll 4
    for (int k = lane; k < H1N; k += 32) {
        float v = H1[(long)row * H1N + k];
        v = fmaxf(0.f, v * scale[k] + shift[k]);
        acc += v * w2[k];
    }
    #pragma unroll
    for (int o = 16; o > 0; o >>= 1) acc += __shfl_xor_sync(0xffffffffu, acc, o);
    if (lane == 0) {
        float logit = acc + b2[0] + lin[row] + bias0[0];
        out[row] = 1.f / (1.f + expf(-logit));
    }
}

// ---------------------------------------------------------------------------
extern "C" void kernel_launch(void* const* d_in, const int* in_sizes, int n_in,
                              void* d_out, int out_size) {
    const int*   x    = (const int*)d_in[0];
    const float* emb  = (const float*)d_in[1];
    const float* lint = (const float*)d_in[2];
    const float* bias = (const float*)d_in[3];
    const float* sw1  = (const float*)d_in[4];
    const float* sw2  = (const float*)d_in[5];
    const float* bilW = (const float*)d_in[6];
    const float* w0   = (const float*)d_in[7];
    const float* b0   = (const float*)d_in[8];
    const float* g0   = (const float*)d_in[9];
    const float* be0  = (const float*)d_in[10];
    const float* w1   = (const float*)d_in[11];
    const float* b1   = (const float*)d_in[12];
    const float* g1   = (const float*)d_in[13];
    const float* be1  = (const float*)d_in[14];
    const float* w2   = (const float*)d_in[15];
    const float* b2   = (const float*)d_in[16];
    float* out = (float*)d_out;

    float *E2r, *WTn, *comb, *h0, *h0t, *h1, *w0t, *w1t, *lin, *sc0, *sh0, *sc1, *sh1;
    cudaGetSymbolAddress((void**)&E2r,  g_E2r);
    cudaGetSymbolAddress((void**)&WTn,  g_WTn);
    cudaGetSymbolAddress((void**)&comb, g_comb);
    cudaGetSymbolAddress((void**)&h0,   g_h0);
    cudaGetSymbolAddress((void**)&h0t,  g_h0t);
    cudaGetSymbolAddress((void**)&h1,   g_h1);
    cudaGetSymbolAddress((void**)&w0t,  g_w0t);
    cudaGetSymbolAddress((void**)&w1t,  g_w1t);
    cudaGetSymbolAddress((void**)&lin,  g_lin);
    cudaGetSymbolAddress((void**)&sc0,  g_scale0);
    cudaGetSymbolAddress((void**)&sh0,  g_shift0);
    cudaGetSymbolAddress((void**)&sc1,  g_scale1);
    cudaGetSymbolAddress((void**)&sh1,  g_shift1);

    // prep (all outputs pre-rounded tf32)
    transposeW_kernel<<<(FD * FD) / 256, 256>>>(bilW, WTn);
    transpose_cvt_kernel<<<dim3(COMB / 32, H0N / 32), dim3(32, 8)>>>(w0, w0t, COMB, H0N);
    transpose_cvt_kernel<<<dim3(H0N / 32, H1N / 32), dim3(32, 8)>>>(w1, w1t, H0N, H1N);
    gather_se_kernel<<<BB, 256>>>(x, emb, lint, sw1, sw2, E2r, lin);
    // G1: comb = (E2r @ WTn^T) * E2r -> [p|q] scatter
    gemm4_kernel<false, true><<<dim3(2 * BB / 128, FD / 128), 128>>>(
        E2r, WTn, comb, 2 * BB, FD, FD, nullptr, E2r);
    // G2: h0 = comb @ w0 + b0
    gemm4_kernel<true, false><<<dim3(BB / 128, H0N / 128), 128>>>(
        comb, w0t, h0, BB, H0N, COMB, b0, nullptr);
    bn_stats_kernel<<<H0N / 32, 512>>>(h0, H0N, g0, be0, sc0, sh0);
    bnrelu_kernel<<<(BB * H0N) / 1024, 256>>>(h0, sc0, sh0, h0t);
    // G3: h1 = h0t @ w1 + b1
    gemm4_kernel<true, false><<<dim3(BB / 128, H1N / 128), 128>>>(
        h0t, w1t, h1, BB, H1N, H0N, b1, nullptr);
    bn_stats_kernel<<<H1N / 32, 512>>>(h1, H1N, g1, be1, sc1, sh1);
    final_kernel<<<BB / 8, 256>>>(h1, sc1, sh1, w2, b2, lin, bias, out);
}

// round 8
// speedup vs baseline: 1.8050x; 1.8050x over previous
#include <cuda_runtime.h>
#include <cuda_fp16.h>
#include <math.h>
#include <stdint.h>

#define BB   4096
#define FF   24
#define VV   1000
#define DD   32
#define FD   768
#define COMB 1536
#define H0N  1024
#define H1N  512
#define RED  8
#define EPSV 1e-5f

// ---------------- device scratch ----------------
__device__ __align__(16) __half g_E2h[2 * BB * FD];   // [e ; A*e] fp16
__device__ __align__(16) __half g_WTn[FD * FD];       // bilinear W as [n=ik][k=jl], diag zero
__device__ __align__(16) __half g_comb[BB * COMB];
__device__ __align__(16) float  g_h0[BB * H0N];
__device__ __align__(16) __half g_h0t[BB * H0N];      // relu(bn(h0)) fp16
__device__ __align__(16) float  g_h1[BB * H1N];
__device__ __align__(16) __half g_w0t[H0N * COMB];    // w0^T [n][k]
__device__ __align__(16) __half g_w1t[H1N * H0N];     // w1^T [n][k]
__device__ float g_lin[BB];
__device__ float g_scale0[H0N], g_shift0[H0N];
__device__ float g_scale1[H1N], g_shift1[H1N];

// ---------------- K0: W -> [ik][jl], diag zeroed, fp16 ---------------------
__global__ void transposeW_kernel(const float* __restrict__ W, __half* __restrict__ WTn) {
    int o = blockIdx.x * 256 + threadIdx.x;        // o = ik*768 + jl
    int jl = o % FD, ik = o / FD;
    int i = ik >> 5, k = ik & 31, j = jl >> 5, l = jl & 31;
    float v = (i == j) ? 0.f : W[(((i * FF + j) * DD + k) * DD) + l];
    WTn[o] = __float2half_rn(v);
}

// ---------------- weight transpose + fp16: [K][N] -> [N][K] ----------------
__global__ void transpose_cvt_kernel(const float* __restrict__ src, __half* __restrict__ dst,
                                     int K, int N) {
    __shared__ float tile[32][33];
    int k0 = blockIdx.x * 32, n0 = blockIdx.y * 32;
    int tx = threadIdx.x, ty = threadIdx.y;        // 32 x 8
    #pragma unroll
    for (int j = 0; j < 4; j++)
        tile[ty + j * 8][tx] = src[(long)(k0 + ty + j * 8) * N + n0 + tx];
    __syncthreads();
    #pragma unroll
    for (int j = 0; j < 4; j++)
        dst[(long)(n0 + ty + j * 8) * K + k0 + tx] = __float2half_rn(tile[tx][ty + j * 8]);
}

// ---------------- K1: gather + linear + SENet -----------------------------
__global__ void gather_se_kernel(const int* __restrict__ x,
                                 const float* __restrict__ emb,
                                 const float* __restrict__ lint,
                                 const float* __restrict__ sw1,
                                 const float* __restrict__ sw2,
                                 __half* __restrict__ E2h,
                                 float* __restrict__ linout) {
    int b = blockIdx.x;
    int t = threadIdx.x;
    __shared__ int   xs[FF];
    __shared__ float es[FD];
    __shared__ float Zs[FF], hid[RED], As[FF], linp[FF];

    if (t < FF) xs[t] = x[b * FF + t];
    __syncthreads();

    #pragma unroll
    for (int r = 0; r < 3; r++) {
        int ik = t + r * 256;
        int f = ik >> 5, d = ik & 31;
        es[ik] = emb[((long)f * VV + xs[f]) * DD + d];
    }
    if (t < FF) linp[t] = lint[(long)t * VV + xs[t]];
    __syncthreads();

    int w = t >> 5, lane = t & 31;
    #pragma unroll
    for (int ff = 0; ff < 3; ff++) {
        int f = w * 3 + ff;
        float v = es[f * 32 + lane];
        #pragma unroll
        for (int o = 16; o > 0; o >>= 1) v += __shfl_xor_sync(0xffffffffu, v, o);
        if (lane == 0) Zs[f] = v * (1.f / 32.f);
    }
    __syncthreads();
    if (t < RED) {
        float s = 0.f;
        #pragma unroll
        for (int f = 0; f < FF; f++) s += Zs[f] * sw1[t * FF + f];
        hid[t] = fmaxf(s, 0.f);
    }
    __syncthreads();
    if (t < FF) {
        float s = 0.f;
        #pragma unroll
        for (int r = 0; r < RED; r++) s += hid[r] * sw2[t * RED + r];
        As[t] = 1.f / (1.f + expf(-s));
    }
    if (t == 0) {
        float s = 0.f;
        #pragma unroll
        for (int f = 0; f < FF; f++) s += linp[f];
        linout[b] = s;
    }
    __syncthreads();

    #pragma unroll
    for (int r = 0; r < 3; r++) {
        int ik = t + r * 256;
        int f = ik >> 5;
        float e = es[ik];
        E2h[(long)b * FD + ik] = __float2half_rn(e);
        E2h[(long)(BB + b) * FD + ik] = __float2half_rn(As[f] * e);
    }
}

// ---------------- fp16 tensor-core GEMM (ldmatrix + m16n8k16) --------------
// 128 thr = 4 warps (2x2); block 128x128; warp 64x64; ktile 16.
// Smem tile: [128 rows][16 halves], 16B chunk c stored at c ^ ((row>>2)&1).
// A[M,K], Bt[N,K] row-major fp16. Double-buffered (flip = +4096B).
template <bool BIAS, bool COMBINE>
__global__ void __launch_bounds__(128, 2)
hgemm_kernel(const __half* __restrict__ A, const __half* __restrict__ Bt,
             float* __restrict__ Cf, __half* __restrict__ Ch,
             int M, int N, int K,
             const float* __restrict__ bias, const __half* __restrict__ E2) {
    __shared__ __align__(16) __half Asm[2][2048];
    __shared__ __align__(16) __half Bsm[2][2048];
    int t = threadIdx.x;
    int m0 = blockIdx.x * 128, n0 = blockIdx.y * 128;
    int wid = t >> 5, lane = t & 31;
    int wm = (wid & 1) * 64, wn = (wid >> 1) * 64;
    int r = lane >> 2, quad = lane & 3;

    float acc[4][8][4];
    #pragma unroll
    for (int mi = 0; mi < 4; mi++)
        #pragma unroll
        for (int ni = 0; ni < 8; ni++)
            #pragma unroll
            for (int c = 0; c < 4; c++) acc[mi][ni][c] = 0.f;

    // staging: thread t -> rows (t>>1) and (t>>1)+64, chunk (t&1)
    int srow = t >> 1, sc = t & 1;
    const __half* Ap = A + (long)(m0 + srow) * K + sc * 8;
    const __half* Bp = Bt + (long)(n0 + srow) * K + sc * 8;
    int swz = (srow >> 2) & 1;                 // same for srow+64
    int s0 = srow * 16 + ((sc ^ swz) << 3);
    int s1 = (srow + 64) * 16 + ((sc ^ swz) << 3);

    // ldmatrix per-lane byte addresses (buffer 0)
    unsigned abase = (unsigned)__cvta_generic_to_shared(Asm[0]);
    unsigned bbase = (unsigned)__cvta_generic_to_shared(Bsm[0]);
    unsigned aaddr[4], baddr[4];
    #pragma unroll
    for (int mi = 0; mi < 4; mi++) {
        int row = wm + mi * 16 + (lane & 7) + ((lane >> 3) & 1) * 8;
        int kc  = (lane >> 4) & 1;
        aaddr[mi] = abase + (unsigned)(row * 16 + ((kc ^ ((row >> 2) & 1)) << 3)) * 2u;
    }
    #pragma unroll
    for (int np = 0; np < 4; np++) {
        int row = wn + np * 16 + (lane & 7) + ((lane >> 4) & 1) * 8;
        int kc  = (lane >> 3) & 1;
        baddr[np] = bbase + (unsigned)(row * 16 + ((kc ^ ((row >> 2) & 1)) << 3)) * 2u;
    }

    uint4 ga0 = *(const uint4*)Ap;
    uint4 ga1 = *(const uint4*)(Ap + 64 * (long)K);
    uint4 gb0 = *(const uint4*)Bp;
    uint4 gb1 = *(const uint4*)(Bp + 64 * (long)K);

    #define STAGE(buf)                                    \
        do {                                              \
            *(uint4*)&Asm[buf][s0] = ga0;                 \
            *(uint4*)&Asm[buf][s1] = ga1;                 \
            *(uint4*)&Bsm[buf][s0] = gb0;                 \
            *(uint4*)&Bsm[buf][s1] = gb1;                 \
        } while (0)

    STAGE(0);
    __syncthreads();

    int buf = 0;
    for (int kt = 0; kt < K; kt += 16) {
        bool more = (kt + 16) < K;
        if (more) {
            ga0 = *(const uint4*)(Ap + kt + 16);
            ga1 = *(const uint4*)(Ap + 64 * (long)K + kt + 16);
            gb0 = *(const uint4*)(Bp + kt + 16);
            gb1 = *(const uint4*)(Bp + 64 * (long)K + kt + 16);
        }
        unsigned boff = (unsigned)buf << 12;       // 4096 bytes per buffer
        unsigned af[4][4], bf[4][4];
        #pragma unroll
        for (int mi = 0; mi < 4; mi++)
            asm volatile("ldmatrix.sync.aligned.m8n8.x4.shared.b16 {%0,%1,%2,%3}, [%4];"
                : "=r"(af[mi][0]), "=r"(af[mi][1]), "=r"(af[mi][2]), "=r"(af[mi][3])
                : "r"(aaddr[mi] + boff));
        #pragma unroll
        for (int np = 0; np < 4; np++)
            asm volatile("ldmatrix.sync.aligned.m8n8.x4.shared.b16 {%0,%1,%2,%3}, [%4];"
                : "=r"(bf[np][0]), "=r"(bf[np][1]), "=r"(bf[np][2]), "=r"(bf[np][3])
                : "r"(baddr[np] + boff));
        #pragma unroll
        for (int mi = 0; mi < 4; mi++)
            #pragma unroll
            for (int ni = 0; ni < 8; ni++) {
                asm volatile(
                    "mma.sync.aligned.m16n8k16.row.col.f32.f16.f16.f32 "
                    "{%0,%1,%2,%3}, {%4,%5,%6,%7}, {%8,%9}, {%0,%1,%2,%3};"
                    : "+f"(acc[mi][ni][0]), "+f"(acc[mi][ni][1]),
                      "+f"(acc[mi][ni][2]), "+f"(acc[mi][ni][3])
                    : "r"(af[mi][0]), "r"(af[mi][1]), "r"(af[mi][2]), "r"(af[mi][3]),
                      "r"(bf[ni >> 1][(ni & 1) * 2]), "r"(bf[ni >> 1][(ni & 1) * 2 + 1]));
            }
        if (more) STAGE(buf ^ 1);
        __syncthreads();
        buf ^= 1;
    }
    #undef STAGE

    // ---- epilogue ----
    #pragma unroll
    for (int mi = 0; mi < 4; mi++) {
        #pragma unroll
        for (int ni = 0; ni < 8; ni++) {
            int row0 = m0 + wm + mi * 16 + r;
            int row1 = row0 + 8;
            int col  = n0 + wn + ni * 8 + 2 * quad;
            float2 v0 = make_float2(acc[mi][ni][0], acc[mi][ni][1]);
            float2 v1 = make_float2(acc[mi][ni][2], acc[mi][ni][3]);
            if (BIAS) {
                float b0v = bias[col], b1v = bias[col + 1];
                v0.x += b0v; v0.y += b1v;
                v1.x += b0v; v1.y += b1v;
            }
            if (COMBINE) {
                float2 e0 = __half22float2(*(const __half2*)&E2[(long)row0 * FD + col]);
                float2 e1 = __half22float2(*(const __half2*)&E2[(long)row1 * FD + col]);
                v0.x *= e0.x; v0.y *= e0.y;
                v1.x *= e1.x; v1.y *= e1.y;
                long br0 = (row0 < BB) ? row0 : (row0 - BB);
                long br1 = (row1 < BB) ? row1 : (row1 - BB);
                int  c0  = (row0 < BB) ? 0 : FD;
                int  c1  = (row1 < BB) ? 0 : FD;
                *(__half2*)&Ch[br0 * (long)COMB + c0 + col] = __floats2half2_rn(v0.x, v0.y);
                *(__half2*)&Ch[br1 * (long)COMB + c1 + col] = __floats2half2_rn(v1.x, v1.y);
            } else {
                *(float2*)&Cf[(long)row0 * N + col] = v0;
                *(float2*)&Cf[(long)row1 * N + col] = v1;
            }
        }
    }
}

// ---------------- BN stats -> scale/shift ----------------------------------
__global__ void bn_stats_kernel(const float* __restrict__ H, int N,
                                const float* __restrict__ g, const float* __restrict__ be,
                                float* __restrict__ scale, float* __restrict__ shift) {
    int lane = threadIdx.x & 31;
    int ty   = threadIdx.x >> 5;
    int col  = blockIdx.x * 32 + lane;
    float s = 0.f, sq = 0.f;
    for (int r = ty; r < BB; r += 16) {
        float v = H[(long)r * N + col];
        s += v; sq += v * v;
    }
    __shared__ float ss[16][33], sqs[16][33];
    ss[ty][lane] = s; sqs[ty][lane] = sq;
    __syncthreads();
    if (ty == 0) {
        #pragma unroll
        for (int i = 1; i < 16; i++) { s += ss[i][lane]; sq += sqs[i][lane]; }
        float mean = s * (1.f / BB);
        float var  = sq * (1.f / BB) - mean * mean;
        float sc   = g[col] * rsqrtf(var + EPSV);
        scale[col] = sc;
        shift[col] = be[col] - mean * sc;
    }
}

// ---------------- relu(bn(h0)) -> fp16 -------------------------------------
__global__ void bnrelu_kernel(const float* __restrict__ H,
                              const float* __restrict__ scale,
                              const float* __restrict__ shift,
                              __half* __restrict__ Ht) {
    int i = (blockIdx.x * 256 + threadIdx.x) * 4;
    int col = i & (H0N - 1);
    float4 v = *(const float4*)&H[i];
    float a = fmaxf(0.f, v.x * scale[col + 0] + shift[col + 0]);
    float b = fmaxf(0.f, v.y * scale[col + 1] + shift[col + 1]);
    float c = fmaxf(0.f, v.z * scale[col + 2] + shift[col + 2]);
    float d = fmaxf(0.f, v.w * scale[col + 3] + shift[col + 3]);
    *(__half2*)&Ht[i]     = __floats2half2_rn(a, b);
    *(__half2*)&Ht[i + 2] = __floats2half2_rn(c, d);
}

// ---------------- final ----------------------------------------------------
__global__ void final_kernel(const float* __restrict__ H1,
                             const float* __restrict__ scale, const float* __restrict__ shift,
                             const float* __restrict__ w2, const float* __restrict__ b2,
                             const float* __restrict__ lin, const float* __restrict__ bias0,
                             float* __restrict__ out) {
    int warp = threadIdx.x >> 5, lane = threadIdx.x & 31;
    int row = blockIdx.x * 8 + warp;
    float acc = 0.f;
    #pragma unroll 4
    for (int k = lane; k < H1N; k += 32) {
        float v = H1[(long)row * H1N + k];
        v = fmaxf(0.f, v * scale[k] + shift[k]);
        acc += v * w2[k];
    }
    #pragma unroll
    for (int o = 16; o > 0; o >>= 1) acc += __shfl_xor_sync(0xffffffffu, acc, o);
    if (lane == 0) {
        float logit = acc + b2[0] + lin[row] + bias0[0];
        out[row] = 1.f / (1.f + expf(-logit));
    }
}

// ---------------------------------------------------------------------------
extern "C" void kernel_launch(void* const* d_in, const int* in_sizes, int n_in,
                              void* d_out, int out_size) {
    const int*   x    = (const int*)d_in[0];
    const float* emb  = (const float*)d_in[1];
    const float* lint = (const float*)d_in[2];
    const float* bias = (const float*)d_in[3];
    const float* sw1  = (const float*)d_in[4];
    const float* sw2  = (const float*)d_in[5];
    const float* bilW = (const float*)d_in[6];
    const float* w0   = (const float*)d_in[7];
    const float* b0   = (const float*)d_in[8];
    const float* g0   = (const float*)d_in[9];
    const float* be0  = (const float*)d_in[10];
    const float* w1   = (const float*)d_in[11];
    const float* b1   = (const float*)d_in[12];
    const float* g1   = (const float*)d_in[13];
    const float* be1  = (const float*)d_in[14];
    const float* w2   = (const float*)d_in[15];
    const float* b2   = (const float*)d_in[16];
    float* out = (float*)d_out;

    __half *E2h, *WTn, *comb, *h0t, *w0t, *w1t;
    float *h0, *h1, *lin, *sc0, *sh0, *sc1, *sh1;
    cudaGetSymbolAddress((void**)&E2h,  g_E2h);
    cudaGetSymbolAddress((void**)&WTn,  g_WTn);
    cudaGetSymbolAddress((void**)&comb, g_comb);
    cudaGetSymbolAddress((void**)&h0,   g_h0);
    cudaGetSymbolAddress((void**)&h0t,  g_h0t);
    cudaGetSymbolAddress((void**)&h1,   g_h1);
    cudaGetSymbolAddress((void**)&w0t,  g_w0t);
    cudaGetSymbolAddress((void**)&w1t,  g_w1t);
    cudaGetSymbolAddress((void**)&lin,  g_lin);
    cudaGetSymbolAddress((void**)&sc0,  g_scale0);
    cudaGetSymbolAddress((void**)&sh0,  g_shift0);
    cudaGetSymbolAddress((void**)&sc1,  g_scale1);
    cudaGetSymbolAddress((void**)&sh1,  g_shift1);

    // prep (fp16 producers)
    transposeW_kernel<<<(FD * FD) / 256, 256>>>(bilW, WTn);
    transpose_cvt_kernel<<<dim3(COMB / 32, H0N / 32), dim3(32, 8)>>>(w0, w0t, COMB, H0N);
    transpose_cvt_kernel<<<dim3(H0N / 32, H1N / 32), dim3(32, 8)>>>(w1, w1t, H0N, H1N);
    gather_se_kernel<<<BB, 256>>>(x, emb, lint, sw1, sw2, E2h, lin);
    // G1: comb = (E2 @ WTn^T) * E2 -> [p|q] scatter (fp16 out)
    hgemm_kernel<false, true><<<dim3(2 * BB / 128, FD / 128), 128>>>(
        E2h, WTn, nullptr, comb, 2 * BB, FD, FD, nullptr, E2h);
    // G2: h0 = comb @ w0 + b0 (fp32 out)
    hgemm_kernel<true, false><<<dim3(BB / 128, H0N / 128), 128>>>(
        comb, w0t, h0, nullptr, BB, H0N, COMB, b0, nullptr);
    bn_stats_kernel<<<H0N / 32, 512>>>(h0, H0N, g0, be0, sc0, sh0);
    bnrelu_kernel<<<(BB * H0N) / 1024, 256>>>(h0, sc0, sh0, h0t);
    // G3: h1 = h0t @ w1 + b1
    hgemm_kernel<true, false><<<dim3(BB / 128, H1N / 128), 128>>>(
        h0t, w1t, h1, nullptr, BB, H1N, H0N, b1, nullptr);
    bn_stats_kernel<<<H1N / 32, 512>>>(h1, H1N, g1, be1, sc1, sh1);
    final_kernel<<<BB / 8, 256>>>(h1, sc1, sh1, w2, b2, lin, bias, out);
}

// round 9
// speedup vs baseline: 2.3862x; 1.3220x over previous
#include <cuda_runtime.h>
#include <cuda_fp16.h>
#include <math.h>
#include <stdint.h>

#define BB   4096
#define FF   24
#define VV   1000
#define DD   32
#define FD   768
#define COMB 1536
#define H0N  1024
#define H1N  512
#define RED  8
#define EPSV 1e-5f

// ---------------- device scratch ----------------
__device__ __align__(16) __half g_E2h[2 * BB * FD];   // [e ; A*e] fp16
__device__ __align__(16) __half g_WTn[FD * FD];       // bilinear W as [n=ik][k=jl], diag zero
__device__ __align__(16) __half g_comb[BB * COMB];
__device__ __align__(16) __half g_h0h[BB * H0N];      // G2 out (pre-BN), fp16
__device__ __align__(16) __half g_h0t[BB * H0N];      // relu(bn(h0)) fp16
__device__ __align__(16) __half g_h1h[BB * H1N];      // G3 out (pre-BN), fp16
__device__ __align__(16) __half g_w0t[H0N * COMB];    // w0^T [n][k]
__device__ __align__(16) __half g_w1t[H1N * H0N];     // w1^T [n][k]
__device__ float g_lin[BB];
__device__ float g_scale0[H0N], g_shift0[H0N];
__device__ float g_scale1[H1N], g_shift1[H1N];

__device__ __forceinline__ void cp16(unsigned dst, const void* src) {
    asm volatile("cp.async.cg.shared.global [%0], [%1], 16;" :: "r"(dst), "l"(src));
}

// ---------------- K0: W -> [ik][jl], diag zeroed, fp16 ---------------------
__global__ void transposeW_kernel(const float* __restrict__ W, __half* __restrict__ WTn) {
    int o = blockIdx.x * 256 + threadIdx.x;        // o = ik*768 + jl
    int jl = o % FD, ik = o / FD;
    int i = ik >> 5, k = ik & 31, j = jl >> 5, l = jl & 31;
    float v = (i == j) ? 0.f : W[(((i * FF + j) * DD + k) * DD) + l];
    WTn[o] = __float2half_rn(v);
}

// ---------------- weight transpose + fp16: [K][N] -> [N][K] ----------------
__global__ void transpose_cvt_kernel(const float* __restrict__ src, __half* __restrict__ dst,
                                     int K, int N) {
    __shared__ float tile[32][33];
    int k0 = blockIdx.x * 32, n0 = blockIdx.y * 32;
    int tx = threadIdx.x, ty = threadIdx.y;        // 32 x 8
    #pragma unroll
    for (int j = 0; j < 4; j++)
        tile[ty + j * 8][tx] = src[(long)(k0 + ty + j * 8) * N + n0 + tx];
    __syncthreads();
    #pragma unroll
    for (int j = 0; j < 4; j++)
        dst[(long)(n0 + ty + j * 8) * K + k0 + tx] = __float2half_rn(tile[tx][ty + j * 8]);
}

// ---------------- K1: gather + linear + SENet -----------------------------
__global__ void gather_se_kernel(const int* __restrict__ x,
                                 const float* __restrict__ emb,
                                 const float* __restrict__ lint,
                                 const float* __restrict__ sw1,
                                 const float* __restrict__ sw2,
                                 __half* __restrict__ E2h,
                                 float* __restrict__ linout) {
    int b = blockIdx.x;
    int t = threadIdx.x;
    __shared__ int   xs[FF];
    __shared__ float es[FD];
    __shared__ float Zs[FF], hid[RED], As[FF], linp[FF];

    if (t < FF) xs[t] = x[b * FF + t];
    __syncthreads();

    #pragma unroll
    for (int r = 0; r < 3; r++) {
        int ik = t + r * 256;
        int f = ik >> 5, d = ik & 31;
        es[ik] = emb[((long)f * VV + xs[f]) * DD + d];
    }
    if (t < FF) linp[t] = lint[(long)t * VV + xs[t]];
    __syncthreads();

    int w = t >> 5, lane = t & 31;
    #pragma unroll
    for (int ff = 0; ff < 3; ff++) {
        int f = w * 3 + ff;
        float v = es[f * 32 + lane];
        #pragma unroll
        for (int o = 16; o > 0; o >>= 1) v += __shfl_xor_sync(0xffffffffu, v, o);
        if (lane == 0) Zs[f] = v * (1.f / 32.f);
    }
    __syncthreads();
    if (t < RED) {
        float s = 0.f;
        #pragma unroll
        for (int f = 0; f < FF; f++) s += Zs[f] * sw1[t * FF + f];
        hid[t] = fmaxf(s, 0.f);
    }
    __syncthreads();
    if (t < FF) {
        float s = 0.f;
        #pragma unroll
        for (int r = 0; r < RED; r++) s += hid[r] * sw2[t * RED + r];
        As[t] = 1.f / (1.f + expf(-s));
    }
    if (t == 0) {
        float s = 0.f;
        #pragma unroll
        for (int f = 0; f < FF; f++) s += linp[f];
        linout[b] = s;
    }
    __syncthreads();

    #pragma unroll
    for (int r = 0; r < 3; r++) {
        int ik = t + r * 256;
        int f = ik >> 5;
        float e = es[ik];
        E2h[(long)b * FD + ik] = __float2half_rn(e);
        E2h[(long)(BB + b) * FD + ik] = __float2half_rn(As[f] * e);
    }
}

// ---------------- fp16 GEMM: ldmatrix + m16n8k16 + cp.async 4-stage --------
// 128 thr = 4 warps (2x2); block 128x128; warp 64x64; ktile 16.
// Smem tile (per 4KB buffer): [128 rows][16 halves], chunk c at c ^ ((row>>2)&1).
// A[M,K], Bt[N,K] row-major fp16. 4 buffers; 1 commit-group per ktile.
template <bool BIAS, bool COMBINE>
__global__ void __launch_bounds__(128, 2)
hgemm_kernel(const __half* __restrict__ A, const __half* __restrict__ Bt,
             __half* __restrict__ C, int M, int N, int K,
             const float* __restrict__ bias, const __half* __restrict__ E2) {
    __shared__ __align__(16) __half Asm[4][2048];
    __shared__ __align__(16) __half Bsm[4][2048];
    int t = threadIdx.x;
    int m0 = blockIdx.x * 128, n0 = blockIdx.y * 128;
    int wid = t >> 5, lane = t & 31;
    int wm = (wid & 1) * 64, wn = (wid >> 1) * 64;
    int r = lane >> 2, quad = lane & 3;

    float acc[4][8][4];
    #pragma unroll
    for (int mi = 0; mi < 4; mi++)
        #pragma unroll
        for (int ni = 0; ni < 8; ni++)
            #pragma unroll
            for (int c = 0; c < 4; c++) acc[mi][ni][c] = 0.f;

    // staging: thread t -> rows (t>>1), (t>>1)+64, 16B chunk (t&1)
    int srow = t >> 1, sc = t & 1;
    const __half* Ap = A + (long)(m0 + srow) * K + sc * 8;
    const __half* Bp = Bt + (long)(n0 + srow) * K + sc * 8;
    int swz = (srow >> 2) & 1;
    unsigned off0 = (unsigned)(srow * 16 + ((sc ^ swz) << 3)) * 2u;
    unsigned off1 = (unsigned)((srow + 64) * 16 + ((sc ^ swz) << 3)) * 2u;

    unsigned abase = (unsigned)__cvta_generic_to_shared(Asm[0]);
    unsigned bbase = (unsigned)__cvta_generic_to_shared(Bsm[0]);

    // ldmatrix per-lane byte addresses (buffer 0)
    unsigned aaddr[4], baddr[4];
    #pragma unroll
    for (int mi = 0; mi < 4; mi++) {
        int row = wm + mi * 16 + (lane & 7) + ((lane >> 3) & 1) * 8;
        int kc  = (lane >> 4) & 1;
        aaddr[mi] = abase + (unsigned)(row * 16 + ((kc ^ ((row >> 2) & 1)) << 3)) * 2u;
    }
    #pragma unroll
    for (int np = 0; np < 4; np++) {
        int row = wn + np * 16 + (lane & 7) + ((lane >> 4) & 1) * 8;
        int kc  = (lane >> 3) & 1;
        baddr[np] = bbase + (unsigned)(row * 16 + ((kc ^ ((row >> 2) & 1)) << 3)) * 2u;
    }

    int nt = K >> 4;
    long rstep = 64 * (long)K;

    #define STAGE(i)                                                        \
        do {                                                                \
            if ((i) < nt) {                                                 \
                unsigned bo = (unsigned)((i) & 3) * 4096u;                  \
                const __half* ak = Ap + (i) * 16;                           \
                const __half* bk = Bp + (i) * 16;                           \
                cp16(abase + bo + off0, ak);                                \
                cp16(abase + bo + off1, ak + rstep);                        \
                cp16(bbase + bo + off0, bk);                                \
                cp16(bbase + bo + off1, bk + rstep);                        \
            }                                                               \
            asm volatile("cp.async.commit_group;");                         \
        } while (0)

    STAGE(0); STAGE(1); STAGE(2);

    for (int i = 0; i < nt; i++) {
        asm volatile("cp.async.wait_group 2;");
        __syncthreads();
        unsigned boff = (unsigned)(i & 3) * 4096u;
        unsigned af[4][4], bf[4][4];
        #pragma unroll
        for (int mi = 0; mi < 4; mi++)
            asm volatile("ldmatrix.sync.aligned.m8n8.x4.shared.b16 {%0,%1,%2,%3}, [%4];"
                : "=r"(af[mi][0]), "=r"(af[mi][1]), "=r"(af[mi][2]), "=r"(af[mi][3])
                : "r"(aaddr[mi] + boff));
        #pragma unroll
        for (int np = 0; np < 4; np++)
            asm volatile("ldmatrix.sync.aligned.m8n8.x4.shared.b16 {%0,%1,%2,%3}, [%4];"
                : "=r"(bf[np][0]), "=r"(bf[np][1]), "=r"(bf[np][2]), "=r"(bf[np][3])
                : "r"(baddr[np] + boff));
        #pragma unroll
        for (int mi = 0; mi < 4; mi++)
            #pragma unroll
            for (int ni = 0; ni < 8; ni++) {
                asm volatile(
                    "mma.sync.aligned.m16n8k16.row.col.f32.f16.f16.f32 "
                    "{%0,%1,%2,%3}, {%4,%5,%6,%7}, {%8,%9}, {%0,%1,%2,%3};"
                    : "+f"(acc[mi][ni][0]), "+f"(acc[mi][ni][1]),
                      "+f"(acc[mi][ni][2]), "+f"(acc[mi][ni][3])
                    : "r"(af[mi][0]), "r"(af[mi][1]), "r"(af[mi][2]), "r"(af[mi][3]),
                      "r"(bf[ni >> 1][(ni & 1) * 2]), "r"(bf[ni >> 1][(ni & 1) * 2 + 1]));
            }
        STAGE(i + 3);
    }
    #undef STAGE
    asm volatile("cp.async.wait_group 0;");

    // ---- epilogue (fp16 out) ----
    #pragma unroll
    for (int mi = 0; mi < 4; mi++) {
        #pragma unroll
        for (int ni = 0; ni < 8; ni++) {
            int row0 = m0 + wm + mi * 16 + r;
            int row1 = row0 + 8;
            int col  = n0 + wn + ni * 8 + 2 * quad;
            float2 v0 = make_float2(acc[mi][ni][0], acc[mi][ni][1]);
            float2 v1 = make_float2(acc[mi][ni][2], acc[mi][ni][3]);
            if (BIAS) {
                float b0v = bias[col], b1v = bias[col + 1];
                v0.x += b0v; v0.y += b1v;
                v1.x += b0v; v1.y += b1v;
            }
            if (COMBINE) {
                float2 e0 = __half22float2(*(const __half2*)&E2[(long)row0 * FD + col]);
                float2 e1 = __half22float2(*(const __half2*)&E2[(long)row1 * FD + col]);
                v0.x *= e0.x; v0.y *= e0.y;
                v1.x *= e1.x; v1.y *= e1.y;
                long br0 = (row0 < BB) ? row0 : (row0 - BB);
                long br1 = (row1 < BB) ? row1 : (row1 - BB);
                int  c0  = (row0 < BB) ? 0 : FD;
                int  c1  = (row1 < BB) ? 0 : FD;
                *(__half2*)&C[br0 * (long)COMB + c0 + col] = __floats2half2_rn(v0.x, v0.y);
                *(__half2*)&C[br1 * (long)COMB + c1 + col] = __floats2half2_rn(v1.x, v1.y);
            } else {
                *(__half2*)&C[(long)row0 * N + col] = __floats2half2_rn(v0.x, v0.y);
                *(__half2*)&C[(long)row1 * N + col] = __floats2half2_rn(v1.x, v1.y);
            }
        }
    }
}

// ---------------- BN stats (fp16 input) -> scale/shift ---------------------
__global__ void bn_stats_kernel(const __half* __restrict__ H, int N,
                                const float* __restrict__ g, const float* __restrict__ be,
                                float* __restrict__ scale, float* __restrict__ shift) {
    int lane = threadIdx.x & 31;
    int ty   = threadIdx.x >> 5;
    int col  = blockIdx.x * 32 + lane;
    float s = 0.f, sq = 0.f;
    for (int r = ty; r < BB; r += 16) {
        float v = __half2float(H[(long)r * N + col]);
        s += v; sq += v * v;
    }
    __shared__ float ss[16][33], sqs[16][33];
    ss[ty][lane] = s; sqs[ty][lane] = sq;
    __syncthreads();
    if (ty == 0) {
        #pragma unroll
        for (int i = 1; i < 16; i++) { s += ss[i][lane]; sq += sqs[i][lane]; }
        float mean = s * (1.f / BB);
        float var  = sq * (1.f / BB) - mean * mean;
        float sc   = g[col] * rsqrtf(var + EPSV);
        scale[col] = sc;
        shift[col] = be[col] - mean * sc;
    }
}

// ---------------- relu(bn(h0)) fp16 -> fp16 --------------------------------
__global__ void bnrelu_kernel(const __half* __restrict__ H,
                              const float* __restrict__ scale,
                              const float* __restrict__ shift,
                              __half* __restrict__ Ht) {
    int i = (blockIdx.x * 256 + threadIdx.x) * 8;
    int col = i & (H0N - 1);
    uint4 raw = *(const uint4*)&H[i];
    const __half2* hp = (const __half2*)&raw;
    uint4 outw;
    __half2* op = (__half2*)&outw;
    #pragma unroll
    for (int j = 0; j < 4; j++) {
        float2 v = __half22float2(hp[j]);
        float a = fmaxf(0.f, v.x * scale[col + 2 * j] + shift[col + 2 * j]);
        float b = fmaxf(0.f, v.y * scale[col + 2 * j + 1] + shift[col + 2 * j + 1]);
        op[j] = __floats2half2_rn(a, b);
    }
    *(uint4*)&Ht[i] = outw;
}

// ---------------- final ----------------------------------------------------
__global__ void final_kernel(const __half* __restrict__ H1,
                             const float* __restrict__ scale, const float* __restrict__ shift,
                             const float* __restrict__ w2, const float* __restrict__ b2,
                             const float* __restrict__ lin, const float* __restrict__ bias0,
                             float* __restrict__ out) {
    int warp = threadIdx.x >> 5, lane = threadIdx.x & 31;
    int row = blockIdx.x * 8 + warp;
    float acc = 0.f;
    #pragma unroll 4
    for (int k = lane; k < H1N; k += 32) {
        float v = __half2float(H1[(long)row * H1N + k]);
        v = fmaxf(0.f, v * scale[k] + shift[k]);
        acc += v * w2[k];
    }
    #pragma unroll
    for (int o = 16; o > 0; o >>= 1) acc += __shfl_xor_sync(0xffffffffu, acc, o);
    if (lane == 0) {
        float logit = acc + b2[0] + lin[row] + bias0[0];
        out[row] = 1.f / (1.f + expf(-logit));
    }
}

// ---------------------------------------------------------------------------
extern "C" void kernel_launch(void* const* d_in, const int* in_sizes, int n_in,
                              void* d_out, int out_size) {
    const int*   x    = (const int*)d_in[0];
    const float* emb  = (const float*)d_in[1];
    const float* lint = (const float*)d_in[2];
    const float* bias = (const float*)d_in[3];
    const float* sw1  = (const float*)d_in[4];
    const float* sw2  = (const float*)d_in[5];
    const float* bilW = (const float*)d_in[6];
    const float* w0   = (const float*)d_in[7];
    const float* b0   = (const float*)d_in[8];
    const float* g0   = (const float*)d_in[9];
    const float* be0  = (const float*)d_in[10];
    const float* w1   = (const float*)d_in[11];
    const float* b1   = (const float*)d_in[12];
    const float* g1   = (const float*)d_in[13];
    const float* be1  = (const float*)d_in[14];
    const float* w2   = (const float*)d_in[15];
    const float* b2   = (const float*)d_in[16];
    float* out = (float*)d_out;

    __half *E2h, *WTn, *comb, *h0h, *h0t, *h1h, *w0t, *w1t;
    float *lin, *sc0, *sh0, *sc1, *sh1;
    cudaGetSymbolAddress((void**)&E2h,  g_E2h);
    cudaGetSymbolAddress((void**)&WTn,  g_WTn);
    cudaGetSymbolAddress((void**)&comb, g_comb);
    cudaGetSymbolAddress((void**)&h0h,  g_h0h);
    cudaGetSymbolAddress((void**)&h0t,  g_h0t);
    cudaGetSymbolAddress((void**)&h1h,  g_h1h);
    cudaGetSymbolAddress((void**)&w0t,  g_w0t);
    cudaGetSymbolAddress((void**)&w1t,  g_w1t);
    cudaGetSymbolAddress((void**)&lin,  g_lin);
    cudaGetSymbolAddress((void**)&sc0,  g_scale0);
    cudaGetSymbolAddress((void**)&sh0,  g_shift0);
    cudaGetSymbolAddress((void**)&sc1,  g_scale1);
    cudaGetSymbolAddress((void**)&sh1,  g_shift1);

    // prep (fp16 producers)
    transposeW_kernel<<<(FD * FD) / 256, 256>>>(bilW, WTn);
    transpose_cvt_kernel<<<dim3(COMB / 32, H0N / 32), dim3(32, 8)>>>(w0, w0t, COMB, H0N);
    transpose_cvt_kernel<<<dim3(H0N / 32, H1N / 32), dim3(32, 8)>>>(w1, w1t, H0N, H1N);
    gather_se_kernel<<<BB, 256>>>(x, emb, lint, sw1, sw2, E2h, lin);
    // G1: comb = (E2 @ WTn^T) * E2 -> [p|q] scatter (fp16)
    hgemm_kernel<false, true><<<dim3(2 * BB / 128, FD / 128), 128>>>(
        E2h, WTn, comb, 2 * BB, FD, FD, nullptr, E2h);
    // G2: h0 = comb @ w0 + b0 (fp16)
    hgemm_kernel<true, false><<<dim3(BB / 128, H0N / 128), 128>>>(
        comb, w0t, h0h, BB, H0N, COMB, b0, nullptr);
    bn_stats_kernel<<<H0N / 32, 512>>>(h0h, H0N, g0, be0, sc0, sh0);
    bnrelu_kernel<<<(BB * H0N) / 2048, 256>>>(h0h, sc0, sh0, h0t);
    // G3: h1 = h0t @ w1 + b1 (fp16)
    hgemm_kernel<true, false><<<dim3(BB / 128, H1N / 128), 128>>>(
        h0t, w1t, h1h, BB, H1N, H0N, b1, nullptr);
    bn_stats_kernel<<<H1N / 32, 512>>>(h1h, H1N, g1, be1, sc1, sh1);
    final_kernel<<<BB / 8, 256>>>(h1h, sc1, sh1, w2, b2, lin, bias, out);
}

// round 10
// speedup vs baseline: 2.4677x; 1.0341x over previous
#include <cuda_runtime.h>
#include <cuda_fp16.h>
#include <math.h>
#include <stdint.h>

#define BB   4096
#define FF   24
#define VV   1000
#define DD   32
#define FD   768
#define COMB 1536
#define H0N  1024
#define H1N  512
#define RED  8
#define EPSV 1e-5f

// prep mega-kernel block ranges (all 256-thread blocks)
#define GB_GATHER 4096
#define GB_TRW    (FD * FD / 256)                 // 2304
#define GB_W0     ((COMB / 32) * (H0N / 32))      // 1536
#define GB_W1     ((H0N / 32) * (H1N / 32))       // 512
#define GB_TOTAL  (GB_GATHER + GB_TRW + GB_W0 + GB_W1)

// ---------------- device scratch ----------------
__device__ __align__(16) __half g_E2h[2 * BB * FD];   // [e ; A*e] fp16
__device__ __align__(16) __half g_WTn[FD * FD];       // bilinear W as [n=ik][k=jl], diag zero
__device__ __align__(16) __half g_comb[BB * COMB];
__device__ __align__(16) __half g_h0h[BB * H0N];      // G2 out (pre-BN)
__device__ __align__(16) __half g_h0t[BB * H0N];      // relu(bn(h0))
__device__ __align__(16) __half g_h1h[BB * H1N];      // G3 out (pre-BN)
__device__ __align__(16) __half g_w0t[H0N * COMB];    // w0^T [n][k]
__device__ __align__(16) __half g_w1t[H1N * H0N];     // w1^T [n][k]
__device__ float g_lin[BB];
__device__ float g_scale0[H0N], g_shift0[H0N];
__device__ float g_scale1[H1N], g_shift1[H1N];

__device__ __forceinline__ void cp16(unsigned dst, const void* src) {
    asm volatile("cp.async.cg.shared.global [%0], [%1], 16;" :: "r"(dst), "l"(src));
}

// ---------------- mega prep kernel -----------------------------------------
// blocks [0, 4096):            gather + SENet + linear  (block b = row)
// blocks [4096, 6400):         bilinear W -> WTn [ik][jl], diag zero
// blocks [6400, 7936):         w0 [K][N] -> w0t [N][K] fp16
// blocks [7936, 8448):         w1 [K][N] -> w1t [N][K] fp16
__global__ void __launch_bounds__(256)
prep_kernel(const int* __restrict__ x,
            const float* __restrict__ emb,
            const float* __restrict__ lint,
            const float* __restrict__ sw1,
            const float* __restrict__ sw2,
            const float* __restrict__ W,
            const float* __restrict__ w0,
            const float* __restrict__ w1,
            __half* __restrict__ E2h,
            __half* __restrict__ WTn,
            __half* __restrict__ w0t,
            __half* __restrict__ w1t,
            float* __restrict__ linout) {
    __shared__ union {
        float tile[32][33];
        struct {
            int   xs[FF];
            float es[FD];
            float Zs[FF], hid[RED], As[FF], linp[FF];
        } g;
    } sm;

    int blk = blockIdx.x;
    int t = threadIdx.x;

    if (blk < GB_GATHER) {
        // ---- gather + SENet + linear ----
        int b = blk;
        if (t < FF) sm.g.xs[t] = x[b * FF + t];
        __syncthreads();

        #pragma unroll
        for (int r = 0; r < 3; r++) {
            int ik = t + r * 256;
            int f = ik >> 5, d = ik & 31;
            sm.g.es[ik] = emb[((long)f * VV + sm.g.xs[f]) * DD + d];
        }
        if (t < FF) sm.g.linp[t] = lint[(long)t * VV + sm.g.xs[t]];
        __syncthreads();

        int w = t >> 5, lane = t & 31;
        #pragma unroll
        for (int ff = 0; ff < 3; ff++) {
            int f = w * 3 + ff;
            float v = sm.g.es[f * 32 + lane];
            #pragma unroll
            for (int o = 16; o > 0; o >>= 1) v += __shfl_xor_sync(0xffffffffu, v, o);
            if (lane == 0) sm.g.Zs[f] = v * (1.f / 32.f);
        }
        __syncthreads();
        if (t < RED) {
            float s = 0.f;
            #pragma unroll
            for (int f = 0; f < FF; f++) s += sm.g.Zs[f] * sw1[t * FF + f];
            sm.g.hid[t] = fmaxf(s, 0.f);
        }
        __syncthreads();
        if (t < FF) {
            float s = 0.f;
            #pragma unroll
            for (int r = 0; r < RED; r++) s += sm.g.hid[r] * sw2[t * RED + r];
            sm.g.As[t] = 1.f / (1.f + expf(-s));
        }
        if (t == 0) {
            float s = 0.f;
            #pragma unroll
            for (int f = 0; f < FF; f++) s += sm.g.linp[f];
            linout[b] = s;
        }
        __syncthreads();

        #pragma unroll
        for (int r = 0; r < 3; r++) {
            int ik = t + r * 256;
            int f = ik >> 5;
            float e = sm.g.es[ik];
            E2h[(long)b * FD + ik] = __float2half_rn(e);
            E2h[(long)(BB + b) * FD + ik] = __float2half_rn(sm.g.As[f] * e);
        }
    } else if (blk < GB_GATHER + GB_TRW) {
        // ---- W -> WTn ----
        int o = (blk - GB_GATHER) * 256 + t;       // o = ik*768 + jl
        int jl = o % FD, ik = o / FD;
        int i = ik >> 5, k = ik & 31, j = jl >> 5, l = jl & 31;
        float v = (i == j) ? 0.f : W[(((i * FF + j) * DD + k) * DD) + l];
        WTn[o] = __float2half_rn(v);
    } else {
        // ---- weight transpose + fp16 ----
        const float* src;
        __half* dst;
        int K, N, kblk, nblk;
        if (blk < GB_GATHER + GB_TRW + GB_W0) {
            int idx = blk - (GB_GATHER + GB_TRW);
            src = w0; dst = w0t; K = COMB; N = H0N;
            kblk = idx % (COMB / 32); nblk = idx / (COMB / 32);
        } else {
            int idx = blk - (GB_GATHER + GB_TRW + GB_W0);
            src = w1; dst = w1t; K = H0N; N = H1N;
            kblk = idx % (H0N / 32); nblk = idx / (H0N / 32);
        }
        int k0 = kblk * 32, n0 = nblk * 32;
        int tx = t & 31, ty = t >> 5;              // 32 x 8
        #pragma unroll
        for (int j = 0; j < 4; j++)
            sm.tile[ty + j * 8][tx] = src[(long)(k0 + ty + j * 8) * N + n0 + tx];
        __syncthreads();
        #pragma unroll
        for (int j = 0; j < 4; j++)
            dst[(long)(n0 + ty + j * 8) * K + k0 + tx] =
                __float2half_rn(sm.tile[tx][ty + j * 8]);
    }
}

// ---------------- fp16 GEMM: ldmatrix + m16n8k16 + cp.async 4-stage --------
// 128 thr = 4 warps (2x2); block 128x128; warp 64x64; ktile 16.
// Smem tile (per 4KB buffer): [128 rows][16 halves], chunk c at c ^ ((row>>2)&1).
// A[M,K], Bt[N,K] row-major fp16. 4 buffers; 1 commit-group per ktile.
template <bool BIAS, bool COMBINE>
__global__ void __launch_bounds__(128, 2)
hgemm_kernel(const __half* __restrict__ A, const __half* __restrict__ Bt,
             __half* __restrict__ C, int M, int N, int K,
             const float* __restrict__ bias, const __half* __restrict__ E2) {
    __shared__ __align__(16) __half Asm[4][2048];
    __shared__ __align__(16) __half Bsm[4][2048];
    int t = threadIdx.x;
    int m0 = blockIdx.x * 128, n0 = blockIdx.y * 128;
    int wid = t >> 5, lane = t & 31;
    int wm = (wid & 1) * 64, wn = (wid >> 1) * 64;
    int r = lane >> 2, quad = lane & 3;

    float acc[4][8][4];
    #pragma unroll
    for (int mi = 0; mi < 4; mi++)
        #pragma unroll
        for (int ni = 0; ni < 8; ni++)
            #pragma unroll
            for (int c = 0; c < 4; c++) acc[mi][ni][c] = 0.f;

    int srow = t >> 1, sc = t & 1;
    const __half* Ap = A + (long)(m0 + srow) * K + sc * 8;
    const __half* Bp = Bt + (long)(n0 + srow) * K + sc * 8;
    int swz = (srow >> 2) & 1;
    unsigned off0 = (unsigned)(srow * 16 + ((sc ^ swz) << 3)) * 2u;
    unsigned off1 = (unsigned)((srow + 64) * 16 + ((sc ^ swz) << 3)) * 2u;

    unsigned abase = (unsigned)__cvta_generic_to_shared(Asm[0]);
    unsigned bbase = (unsigned)__cvta_generic_to_shared(Bsm[0]);

    unsigned aaddr[4], baddr[4];
    #pragma unroll
    for (int mi = 0; mi < 4; mi++) {
        int row = wm + mi * 16 + (lane & 7) + ((lane >> 3) & 1) * 8;
        int kc  = (lane >> 4) & 1;
        aaddr[mi] = abase + (unsigned)(row * 16 + ((kc ^ ((row >> 2) & 1)) << 3)) * 2u;
    }
    #pragma unroll
    for (int np = 0; np < 4; np++) {
        int row = wn + np * 16 + (lane & 7) + ((lane >> 4) & 1) * 8;
        int kc  = (lane >> 3) & 1;
        baddr[np] = bbase + (unsigned)(row * 16 + ((kc ^ ((row >> 2) & 1)) << 3)) * 2u;
    }

    int nt = K >> 4;
    long rstep = 64 * (long)K;

    #define STAGE(i)                                                        \
        do {                                                                \
            if ((i) < nt) {                                                 \
                unsigned bo = (unsigned)((i) & 3) * 4096u;                  \
                const __half* ak = Ap + (i) * 16;                           \
                const __half* bk = Bp + (i) * 16;                           \
                cp16(abase + bo + off0, ak);                                \
                cp16(abase + bo + off1, ak + rstep);                        \
                cp16(bbase + bo + off0, bk);                                \
                cp16(bbase + bo + off1, bk + rstep);                        \
            }                                                               \
            asm volatile("cp.async.commit_group;");                         \
        } while (0)

    STAGE(0); STAGE(1); STAGE(2);

    for (int i = 0; i < nt; i++) {
        asm volatile("cp.async.wait_group 2;");
        __syncthreads();
        unsigned boff = (unsigned)(i & 3) * 4096u;
        unsigned af[4][4], bf[4][4];
        #pragma unroll
        for (int mi = 0; mi < 4; mi++)
            asm volatile("ldmatrix.sync.aligned.m8n8.x4.shared.b16 {%0,%1,%2,%3}, [%4];"
                : "=r"(af[mi][0]), "=r"(af[mi][1]), "=r"(af[mi][2]), "=r"(af[mi][3])
                : "r"(aaddr[mi] + boff));
        #pragma unroll
        for (int np = 0; np < 4; np++)
            asm volatile("ldmatrix.sync.aligned.m8n8.x4.shared.b16 {%0,%1,%2,%3}, [%4];"
                : "=r"(bf[np][0]), "=r"(bf[np][1]), "=r"(bf[np][2]), "=r"(bf[np][3])
                : "r"(baddr[np] + boff));
        #pragma unroll
        for (int mi = 0; mi < 4; mi++)
            #pragma unroll
            for (int ni = 0; ni < 8; ni++) {
                asm volatile(
                    "mma.sync.aligned.m16n8k16.row.col.f32.f16.f16.f32 "
                    "{%0,%1,%2,%3}, {%4,%5,%6,%7}, {%8,%9}, {%0,%1,%2,%3};"
                    : "+f"(acc[mi][ni][0]), "+f"(acc[mi][ni][1]),
                      "+f"(acc[mi][ni][2]), "+f"(acc[mi][ni][3])
                    : "r"(af[mi][0]), "r"(af[mi][1]), "r"(af[mi][2]), "r"(af[mi][3]),
                      "r"(bf[ni >> 1][(ni & 1) * 2]), "r"(bf[ni >> 1][(ni & 1) * 2 + 1]));
            }
        STAGE(i + 3);
    }
    #undef STAGE
    asm volatile("cp.async.wait_group 0;");

    // ---- epilogue (fp16 out) ----
    #pragma unroll
    for (int mi = 0; mi < 4; mi++) {
        #pragma unroll
        for (int ni = 0; ni < 8; ni++) {
            int row0 = m0 + wm + mi * 16 + r;
            int row1 = row0 + 8;
            int col  = n0 + wn + ni * 8 + 2 * quad;
            float2 v0 = make_float2(acc[mi][ni][0], acc[mi][ni][1]);
            float2 v1 = make_float2(acc[mi][ni][2], acc[mi][ni][3]);
            if (BIAS) {
                float b0v = bias[col], b1v = bias[col + 1];
                v0.x += b0v; v0.y += b1v;
                v1.x += b0v; v1.y += b1v;
            }
            if (COMBINE) {
                float2 e0 = __half22float2(*(const __half2*)&E2[(long)row0 * FD + col]);
                float2 e1 = __half22float2(*(const __half2*)&E2[(long)row1 * FD + col]);
                v0.x *= e0.x; v0.y *= e0.y;
                v1.x *= e1.x; v1.y *= e1.y;
                long br0 = (row0 < BB) ? row0 : (row0 - BB);
                long br1 = (row1 < BB) ? row1 : (row1 - BB);
                int  c0  = (row0 < BB) ? 0 : FD;
                int  c1  = (row1 < BB) ? 0 : FD;
                *(__half2*)&C[br0 * (long)COMB + c0 + col] = __floats2half2_rn(v0.x, v0.y);
                *(__half2*)&C[br1 * (long)COMB + c1 + col] = __floats2half2_rn(v1.x, v1.y);
            } else {
                *(__half2*)&C[(long)row0 * N + col] = __floats2half2_rn(v0.x, v0.y);
                *(__half2*)&C[(long)row1 * N + col] = __floats2half2_rn(v1.x, v1.y);
            }
        }
    }
}

// ---------------- BN stats (fp16 input) -> scale/shift ---------------------
__global__ void bn_stats_kernel(const __half* __restrict__ H, int N,
                                const float* __restrict__ g, const float* __restrict__ be,
                                float* __restrict__ scale, float* __restrict__ shift) {
    int lane = threadIdx.x & 31;
    int ty   = threadIdx.x >> 5;
    int col  = blockIdx.x * 32 + lane;
    float s = 0.f, sq = 0.f;
    for (int r = ty; r < BB; r += 16) {
        float v = __half2float(H[(long)r * N + col]);
        s += v; sq += v * v;
    }
    __shared__ float ss[16][33], sqs[16][33];
    ss[ty][lane] = s; sqs[ty][lane] = sq;
    __syncthreads();
    if (ty == 0) {
        #pragma unroll
        for (int i = 1; i < 16; i++) { s += ss[i][lane]; sq += sqs[i][lane]; }
        float mean = s * (1.f / BB);
        float var  = sq * (1.f / BB) - mean * mean;
        float sc   = g[col] * rsqrtf(var + EPSV);
        scale[col] = sc;
        shift[col] = be[col] - mean * sc;
    }
}

// ---------------- relu(bn(h0)) fp16 -> fp16 --------------------------------
__global__ void bnrelu_kernel(const __half* __restrict__ H,
                              const float* __restrict__ scale,
                              const float* __restrict__ shift,
                              __half* __restrict__ Ht) {
    int i = (blockIdx.x * 256 + threadIdx.x) * 8;
    int col = i & (H0N - 1);
    uint4 raw = *(const uint4*)&H[i];
    const __half2* hp = (const __half2*)&raw;
    uint4 outw;
    __half2* op = (__half2*)&outw;
    #pragma unroll
    for (int j = 0; j < 4; j++) {
        float2 v = __half22float2(hp[j]);
        float a = fmaxf(0.f, v.x * scale[col + 2 * j] + shift[col + 2 * j]);
        float b = fmaxf(0.f, v.y * scale[col + 2 * j + 1] + shift[col + 2 * j + 1]);
        op[j] = __floats2half2_rn(a, b);
    }
    *(uint4*)&Ht[i] = outw;
}

// ---------------- final ----------------------------------------------------
__global__ void final_kernel(const __half* __restrict__ H1,
                             const float* __restrict__ scale, const float* __restrict__ shift,
                             const float* __restrict__ w2, const float* __restrict__ b2,
                             const float* __restrict__ lin, const float* __restrict__ bias0,
                             float* __restrict__ out) {
    int warp = threadIdx.x >> 5, lane = threadIdx.x & 31;
    int row = blockIdx.x * 8 + warp;
    float acc = 0.f;
    #pragma unroll 4
    for (int k = lane; k < H1N; k += 32) {
        float v = __half2float(H1[(long)row * H1N + k]);
        v = fmaxf(0.f, v * scale[k] + shift[k]);
        acc += v * w2[k];
    }
    #pragma unroll
    for (int o = 16; o > 0; o >>= 1) acc += __shfl_xor_sync(0xffffffffu, acc, o);
    if (lane == 0) {
        float logit = acc + b2[0] + lin[row] + bias0[0];
        out[row] = 1.f / (1.f + expf(-logit));
    }
}

// ---------------------------------------------------------------------------
extern "C" void kernel_launch(void* const* d_in, const int* in_sizes, int n_in,
                              void* d_out, int out_size) {
    const int*   x    = (const int*)d_in[0];
    const float* emb  = (const float*)d_in[1];
    const float* lint = (const float*)d_in[2];
    const float* bias = (const float*)d_in[3];
    const float* sw1  = (const float*)d_in[4];
    const float* sw2  = (const float*)d_in[5];
    const float* bilW = (const float*)d_in[6];
    const float* w0   = (const float*)d_in[7];
    const float* b0   = (const float*)d_in[8];
    const float* g0   = (const float*)d_in[9];
    const float* be0  = (const float*)d_in[10];
    const float* w1   = (const float*)d_in[11];
    const float* b1   = (const float*)d_in[12];
    const float* g1   = (const float*)d_in[13];
    const float* be1  = (const float*)d_in[14];
    const float* w2   = (const float*)d_in[15];
    const float* b2   = (const float*)d_in[16];
    float* out = (float*)d_out;

    __half *E2h, *WTn, *comb, *h0h, *h0t, *h1h, *w0t, *w1t;
    float *lin, *sc0, *sh0, *sc1, *sh1;
    cudaGetSymbolAddress((void**)&E2h,  g_E2h);
    cudaGetSymbolAddress((void**)&WTn,  g_WTn);
    cudaGetSymbolAddress((void**)&comb, g_comb);
    cudaGetSymbolAddress((void**)&h0h,  g_h0h);
    cudaGetSymbolAddress((void**)&h0t,  g_h0t);
    cudaGetSymbolAddress((void**)&h1h,  g_h1h);
    cudaGetSymbolAddress((void**)&w0t,  g_w0t);
    cudaGetSymbolAddress((void**)&w1t,  g_w1t);
    cudaGetSymbolAddress((void**)&lin,  g_lin);
    cudaGetSymbolAddress((void**)&sc0,  g_scale0);
    cudaGetSymbolAddress((void**)&sh0,  g_shift0);
    cudaGetSymbolAddress((void**)&sc1,  g_scale1);
    cudaGetSymbolAddress((void**)&sh1,  g_shift1);

    // P: all independent producers in one launch (gather blocks first)
    prep_kernel<<<GB_TOTAL, 256>>>(x, emb, lint, sw1, sw2, bilW, w0, w1,
                                   E2h, WTn, w0t, w1t, lin);
    // G1: comb = (E2 @ WTn^T) * E2 -> [p|q] scatter (fp16)
    hgemm_kernel<false, true><<<dim3(2 * BB / 128, FD / 128), 128>>>(
        E2h, WTn, comb, 2 * BB, FD, FD, nullptr, E2h);
    // G2: h0 = comb @ w0 + b0 (fp16)
    hgemm_kernel<true, false><<<dim3(BB / 128, H0N / 128), 128>>>(
        comb, w0t, h0h, BB, H0N, COMB, b0, nullptr);
    bn_stats_kernel<<<H0N / 32, 512>>>(h0h, H0N, g0, be0, sc0, sh0);
    bnrelu_kernel<<<(BB * H0N) / 2048, 256>>>(h0h, sc0, sh0, h0t);
    // G3: h1 = h0t @ w1 + b1 (fp16)
    hgemm_kernel<true, false><<<dim3(BB / 128, H1N / 128), 128>>>(
        h0t, w1t, h1h, BB, H1N, H0N, b1, nullptr);
    bn_stats_kernel<<<H1N / 32, 512>>>(h1h, H1N, g1, be1, sc1, sh1);
    final_kernel<<<BB / 8, 256>>>(h1h, sc1, sh1, w2, b2, lin, bias, out);
}

// round 11
// speedup vs baseline: 3.1715x; 1.2852x over previous
#include <cuda_runtime.h>
#include <cuda_fp16.h>
#include <math.h>
#include <stdint.h>

#define BB   4096
#define FF   24
#define VV   1000
#define DD   32
#define FD   768
#define COMB 1536
#define H0N  1024
#define H1N  512
#define RED  8
#define EPSV 1e-5f
#define RCH  32            // row chunks for BN phase-1 (BB/128)

// prep mega-kernel block ranges (all 256-thread blocks)
#define GB_GATHER 4096
#define GB_TRW    (FD * FD / 256)                 // 2304
#define GB_W0     ((COMB / 32) * (H0N / 32))      // 1536
#define GB_W1     ((H0N / 32) * (H1N / 32))       // 512
#define GB_TOTAL  (GB_GATHER + GB_TRW + GB_W0 + GB_W1)

// ---------------- device scratch ----------------
__device__ __align__(16) __half g_E2h[2 * BB * FD];
__device__ __align__(16) __half g_WTn[FD * FD];
__device__ __align__(16) __half g_comb[BB * COMB];
__device__ __align__(16) __half g_h0h[BB * H0N];
__device__ __align__(16) __half g_h0t[BB * H0N];
__device__ __align__(16) __half g_h1h[BB * H1N];
__device__ __align__(16) __half g_w0t[H0N * COMB];
__device__ __align__(16) __half g_w1t[H1N * H0N];
__device__ float g_lin[BB];
__device__ float g_scale0[H0N], g_shift0[H0N];
__device__ float g_scale1[H1N], g_shift1[H1N];
__device__ __align__(16) float g_ps[RCH * H0N];   // BN phase-1 partial sums
__device__ __align__(16) float g_psq[RCH * H0N];  // BN phase-1 partial sumsq

__device__ __forceinline__ void cp16(unsigned dst, const void* src) {
    asm volatile("cp.async.cg.shared.global [%0], [%1], 16;" :: "r"(dst), "l"(src));
}

// ---------------- mega prep kernel -----------------------------------------
__global__ void __launch_bounds__(256)
prep_kernel(const int* __restrict__ x,
            const float* __restrict__ emb,
            const float* __restrict__ lint,
            const float* __restrict__ sw1,
            const float* __restrict__ sw2,
            const float* __restrict__ W,
            const float* __restrict__ w0,
            const float* __restrict__ w1,
            __half* __restrict__ E2h,
            __half* __restrict__ WTn,
            __half* __restrict__ w0t,
            __half* __restrict__ w1t,
            float* __restrict__ linout) {
    __shared__ union {
        float tile[32][33];
        struct {
            int   xs[FF];
            float es[FD];
            float Zs[FF], hid[RED], As[FF], linp[FF];
        } g;
    } sm;

    int blk = blockIdx.x;
    int t = threadIdx.x;

    if (blk < GB_GATHER) {
        int b = blk;
        if (t < FF) sm.g.xs[t] = x[b * FF + t];
        __syncthreads();

        #pragma unroll
        for (int r = 0; r < 3; r++) {
            int ik = t + r * 256;
            int f = ik >> 5, d = ik & 31;
            sm.g.es[ik] = emb[((long)f * VV + sm.g.xs[f]) * DD + d];
        }
        if (t < FF) sm.g.linp[t] = lint[(long)t * VV + sm.g.xs[t]];
        __syncthreads();

        int w = t >> 5, lane = t & 31;
        #pragma unroll
        for (int ff = 0; ff < 3; ff++) {
            int f = w * 3 + ff;
            float v = sm.g.es[f * 32 + lane];
            #pragma unroll
            for (int o = 16; o > 0; o >>= 1) v += __shfl_xor_sync(0xffffffffu, v, o);
            if (lane == 0) sm.g.Zs[f] = v * (1.f / 32.f);
        }
        __syncthreads();
        if (t < RED) {
            float s = 0.f;
            #pragma unroll
            for (int f = 0; f < FF; f++) s += sm.g.Zs[f] * sw1[t * FF + f];
            sm.g.hid[t] = fmaxf(s, 0.f);
        }
        __syncthreads();
        if (t < FF) {
            float s = 0.f;
            #pragma unroll
            for (int r = 0; r < RED; r++) s += sm.g.hid[r] * sw2[t * RED + r];
            sm.g.As[t] = 1.f / (1.f + expf(-s));
        }
        if (t == 0) {
            float s = 0.f;
            #pragma unroll
            for (int f = 0; f < FF; f++) s += sm.g.linp[f];
            linout[b] = s;
        }
        __syncthreads();

        #pragma unroll
        for (int r = 0; r < 3; r++) {
            int ik = t + r * 256;
            int f = ik >> 5;
            float e = sm.g.es[ik];
            E2h[(long)b * FD + ik] = __float2half_rn(e);
            E2h[(long)(BB + b) * FD + ik] = __float2half_rn(sm.g.As[f] * e);
        }
    } else if (blk < GB_GATHER + GB_TRW) {
        int o = (blk - GB_GATHER) * 256 + t;
        int jl = o % FD, ik = o / FD;
        int i = ik >> 5, k = ik & 31, j = jl >> 5, l = jl & 31;
        float v = (i == j) ? 0.f : W[(((i * FF + j) * DD + k) * DD) + l];
        WTn[o] = __float2half_rn(v);
    } else {
        const float* src;
        __half* dst;
        int K, N, kblk, nblk;
        if (blk < GB_GATHER + GB_TRW + GB_W0) {
            int idx = blk - (GB_GATHER + GB_TRW);
            src = w0; dst = w0t; K = COMB; N = H0N;
            kblk = idx % (COMB / 32); nblk = idx / (COMB / 32);
        } else {
            int idx = blk - (GB_GATHER + GB_TRW + GB_W0);
            src = w1; dst = w1t; K = H0N; N = H1N;
            kblk = idx % (H0N / 32); nblk = idx / (H0N / 32);
        }
        int k0 = kblk * 32, n0 = nblk * 32;
        int tx = t & 31, ty = t >> 5;
        #pragma unroll
        for (int j = 0; j < 4; j++)
            sm.tile[ty + j * 8][tx] = src[(long)(k0 + ty + j * 8) * N + n0 + tx];
        __syncthreads();
        #pragma unroll
        for (int j = 0; j < 4; j++)
            dst[(long)(n0 + ty + j * 8) * K + k0 + tx] =
                __float2half_rn(sm.tile[tx][ty + j * 8]);
    }
}

// ---------------- fp16 GEMM: ldmatrix + m16n8k16 + cp.async 4-stage --------
template <bool BIAS, bool COMBINE>
__global__ void __launch_bounds__(128, 2)
hgemm_kernel(const __half* __restrict__ A, const __half* __restrict__ Bt,
             __half* __restrict__ C, int M, int N, int K,
             const float* __restrict__ bias, const __half* __restrict__ E2) {
    __shared__ __align__(16) __half Asm[4][2048];
    __shared__ __align__(16) __half Bsm[4][2048];
    int t = threadIdx.x;
    int m0 = blockIdx.x * 128, n0 = blockIdx.y * 128;
    int wid = t >> 5, lane = t & 31;
    int wm = (wid & 1) * 64, wn = (wid >> 1) * 64;
    int r = lane >> 2, quad = lane & 3;

    float acc[4][8][4];
    #pragma unroll
    for (int mi = 0; mi < 4; mi++)
        #pragma unroll
        for (int ni = 0; ni < 8; ni++)
            #pragma unroll
            for (int c = 0; c < 4; c++) acc[mi][ni][c] = 0.f;

    int srow = t >> 1, sc = t & 1;
    const __half* Ap = A + (long)(m0 + srow) * K + sc * 8;
    const __half* Bp = Bt + (long)(n0 + srow) * K + sc * 8;
    int swz = (srow >> 2) & 1;
    unsigned off0 = (unsigned)(srow * 16 + ((sc ^ swz) << 3)) * 2u;
    unsigned off1 = (unsigned)((srow + 64) * 16 + ((sc ^ swz) << 3)) * 2u;

    unsigned abase = (unsigned)__cvta_generic_to_shared(Asm[0]);
    unsigned bbase = (unsigned)__cvta_generic_to_shared(Bsm[0]);

    unsigned aaddr[4], baddr[4];
    #pragma unroll
    for (int mi = 0; mi < 4; mi++) {
        int row = wm + mi * 16 + (lane & 7) + ((lane >> 3) & 1) * 8;
        int kc  = (lane >> 4) & 1;
        aaddr[mi] = abase + (unsigned)(row * 16 + ((kc ^ ((row >> 2) & 1)) << 3)) * 2u;
    }
    #pragma unroll
    for (int np = 0; np < 4; np++) {
        int row = wn + np * 16 + (lane & 7) + ((lane >> 4) & 1) * 8;
        int kc  = (lane >> 3) & 1;
        baddr[np] = bbase + (unsigned)(row * 16 + ((kc ^ ((row >> 2) & 1)) << 3)) * 2u;
    }

    int nt = K >> 4;
    long rstep = 64 * (long)K;

    #define STAGE(i)                                                        \
        do {                                                                \
            if ((i) < nt) {                                                 \
                unsigned bo = (unsigned)((i) & 3) * 4096u;                  \
                const __half* ak = Ap + (i) * 16;                           \
                const __half* bk = Bp + (i) * 16;                           \
                cp16(abase + bo + off0, ak);                                \
                cp16(abase + bo + off1, ak + rstep);                        \
                cp16(bbase + bo + off0, bk);                                \
                cp16(bbase + bo + off1, bk + rstep);                        \
            }                                                               \
            asm volatile("cp.async.commit_group;");                         \
        } while (0)

    STAGE(0); STAGE(1); STAGE(2);

    for (int i = 0; i < nt; i++) {
        asm volatile("cp.async.wait_group 2;");
        __syncthreads();
        unsigned boff = (unsigned)(i & 3) * 4096u;
        unsigned af[4][4], bf[4][4];
        #pragma unroll
        for (int mi = 0; mi < 4; mi++)
            asm volatile("ldmatrix.sync.aligned.m8n8.x4.shared.b16 {%0,%1,%2,%3}, [%4];"
                : "=r"(af[mi][0]), "=r"(af[mi][1]), "=r"(af[mi][2]), "=r"(af[mi][3])
                : "r"(aaddr[mi] + boff));
        #pragma unroll
        for (int np = 0; np < 4; np++)
            asm volatile("ldmatrix.sync.aligned.m8n8.x4.shared.b16 {%0,%1,%2,%3}, [%4];"
                : "=r"(bf[np][0]), "=r"(bf[np][1]), "=r"(bf[np][2]), "=r"(bf[np][3])
                : "r"(baddr[np] + boff));
        #pragma unroll
        for (int mi = 0; mi < 4; mi++)
            #pragma unroll
            for (int ni = 0; ni < 8; ni++) {
                asm volatile(
                    "mma.sync.aligned.m16n8k16.row.col.f32.f16.f16.f32 "
                    "{%0,%1,%2,%3}, {%4,%5,%6,%7}, {%8,%9}, {%0,%1,%2,%3};"
                    : "+f"(acc[mi][ni][0]), "+f"(acc[mi][ni][1]),
                      "+f"(acc[mi][ni][2]), "+f"(acc[mi][ni][3])
                    : "r"(af[mi][0]), "r"(af[mi][1]), "r"(af[mi][2]), "r"(af[mi][3]),
                      "r"(bf[ni >> 1][(ni & 1) * 2]), "r"(bf[ni >> 1][(ni & 1) * 2 + 1]));
            }
        STAGE(i + 3);
    }
    #undef STAGE
    asm volatile("cp.async.wait_group 0;");

    #pragma unroll
    for (int mi = 0; mi < 4; mi++) {
        #pragma unroll
        for (int ni = 0; ni < 8; ni++) {
            int row0 = m0 + wm + mi * 16 + r;
            int row1 = row0 + 8;
            int col  = n0 + wn + ni * 8 + 2 * quad;
            float2 v0 = make_float2(acc[mi][ni][0], acc[mi][ni][1]);
            float2 v1 = make_float2(acc[mi][ni][2], acc[mi][ni][3]);
            if (BIAS) {
                float b0v = bias[col], b1v = bias[col + 1];
                v0.x += b0v; v0.y += b1v;
                v1.x += b0v; v1.y += b1v;
            }
            if (COMBINE) {
                float2 e0 = __half22float2(*(const __half2*)&E2[(long)row0 * FD + col]);
                float2 e1 = __half22float2(*(const __half2*)&E2[(long)row1 * FD + col]);
                v0.x *= e0.x; v0.y *= e0.y;
                v1.x *= e1.x; v1.y *= e1.y;
                long br0 = (row0 < BB) ? row0 : (row0 - BB);
                long br1 = (row1 < BB) ? row1 : (row1 - BB);
                int  c0  = (row0 < BB) ? 0 : FD;
                int  c1  = (row1 < BB) ? 0 : FD;
                *(__half2*)&C[br0 * (long)COMB + c0 + col] = __floats2half2_rn(v0.x, v0.y);
                *(__half2*)&C[br1 * (long)COMB + c1 + col] = __floats2half2_rn(v1.x, v1.y);
            } else {
                *(__half2*)&C[(long)row0 * N + col] = __floats2half2_rn(v0.x, v0.y);
                *(__half2*)&C[(long)row1 * N + col] = __floats2half2_rn(v1.x, v1.y);
            }
        }
    }
}

// ---------------- BN stats phase 1: partial sums per 128-row chunk ---------
// grid (N/64, RCH); block 256 = 32 lanes x 8 rowwalkers; lane covers 2 cols.
__global__ void __launch_bounds__(256)
bn_part_kernel(const __half* __restrict__ H, int N,
               float* __restrict__ ps, float* __restrict__ psq) {
    int lane = threadIdx.x & 31;
    int ty   = threadIdx.x >> 5;                   // 0..7
    int col  = blockIdx.x * 64 + lane * 2;
    int r0   = blockIdx.y * 128;
    float s0 = 0.f, s1 = 0.f, q0 = 0.f, q1 = 0.f;
    #pragma unroll 4
    for (int r = ty; r < 128; r += 8) {
        float2 v = __half22float2(*(const __half2*)&H[(long)(r0 + r) * N + col]);
        s0 += v.x; s1 += v.y;
        q0 += v.x * v.x; q1 += v.y * v.y;
    }
    __shared__ float sm[8][32][4];
    sm[ty][lane][0] = s0; sm[ty][lane][1] = s1;
    sm[ty][lane][2] = q0; sm[ty][lane][3] = q1;
    __syncthreads();
    if (ty == 0) {
        #pragma unroll
        for (int i = 1; i < 8; i++) {
            s0 += sm[i][lane][0]; s1 += sm[i][lane][1];
            q0 += sm[i][lane][2]; q1 += sm[i][lane][3];
        }
        long o = (long)blockIdx.y * N + col;
        ps[o] = s0;  ps[o + 1] = s1;
        psq[o] = q0; psq[o + 1] = q1;
    }
}

// ---------------- BN stats phase 2: finalize -> scale/shift ----------------
__global__ void __launch_bounds__(256)
bn_fin_kernel(const float* __restrict__ ps, const float* __restrict__ psq, int N,
              const float* __restrict__ g, const float* __restrict__ be,
              float* __restrict__ scale, float* __restrict__ shift) {
    int col = blockIdx.x * 256 + threadIdx.x;
    float s = 0.f, q = 0.f;
    #pragma unroll
    for (int i = 0; i < RCH; i++) {
        s += ps[(long)i * N + col];
        q += psq[(long)i * N + col];
    }
    float mean = s * (1.f / BB);
    float var  = q * (1.f / BB) - mean * mean;
    float sc   = g[col] * rsqrtf(var + EPSV);
    scale[col] = sc;
    shift[col] = be[col] - mean * sc;
}

// ---------------- relu(bn(h0)) fp16 -> fp16 --------------------------------
__global__ void bnrelu_kernel(const __half* __restrict__ H,
                              const float* __restrict__ scale,
                              const float* __restrict__ shift,
                              __half* __restrict__ Ht) {
    int i = (blockIdx.x * 256 + threadIdx.x) * 8;
    int col = i & (H0N - 1);
    uint4 raw = *(const uint4*)&H[i];
    const __half2* hp = (const __half2*)&raw;
    uint4 outw;
    __half2* op = (__half2*)&outw;
    #pragma unroll
    for (int j = 0; j < 4; j++) {
        float2 v = __half22float2(hp[j]);
        float a = fmaxf(0.f, v.x * scale[col + 2 * j] + shift[col + 2 * j]);
        float b = fmaxf(0.f, v.y * scale[col + 2 * j + 1] + shift[col + 2 * j + 1]);
        op[j] = __floats2half2_rn(a, b);
    }
    *(uint4*)&Ht[i] = outw;
}

// ---------------- final ----------------------------------------------------
__global__ void final_kernel(const __half* __restrict__ H1,
                             const float* __restrict__ scale, const float* __restrict__ shift,
                             const float* __restrict__ w2, const float* __restrict__ b2,
                             const float* __restrict__ lin, const float* __restrict__ bias0,
                             float* __restrict__ out) {
    int warp = threadIdx.x >> 5, lane = threadIdx.x & 31;
    int row = blockIdx.x * 8 + warp;
    float acc = 0.f;
    #pragma unroll 4
    for (int k = lane; k < H1N; k += 32) {
        float v = __half2float(H1[(long)row * H1N + k]);
        v = fmaxf(0.f, v * scale[k] + shift[k]);
        acc += v * w2[k];
    }
    #pragma unroll
    for (int o = 16; o > 0; o >>= 1) acc += __shfl_xor_sync(0xffffffffu, acc, o);
    if (lane == 0) {
        float logit = acc + b2[0] + lin[row] + bias0[0];
        out[row] = 1.f / (1.f + expf(-logit));
    }
}

// ---------------------------------------------------------------------------
extern "C" void kernel_launch(void* const* d_in, const int* in_sizes, int n_in,
                              void* d_out, int out_size) {
    const int*   x    = (const int*)d_in[0];
    const float* emb  = (const float*)d_in[1];
    const float* lint = (const float*)d_in[2];
    const float* bias = (const float*)d_in[3];
    const float* sw1  = (const float*)d_in[4];
    const float* sw2  = (const float*)d_in[5];
    const float* bilW = (const float*)d_in[6];
    const float* w0   = (const float*)d_in[7];
    const float* b0   = (const float*)d_in[8];
    const float* g0   = (const float*)d_in[9];
    const float* be0  = (const float*)d_in[10];
    const float* w1   = (const float*)d_in[11];
    const float* b1   = (const float*)d_in[12];
    const float* g1   = (const float*)d_in[13];
    const float* be1  = (const float*)d_in[14];
    const float* w2   = (const float*)d_in[15];
    const float* b2   = (const float*)d_in[16];
    float* out = (float*)d_out;

    __half *E2h, *WTn, *comb, *h0h, *h0t, *h1h, *w0t, *w1t;
    float *lin, *sc0, *sh0, *sc1, *sh1, *ps, *psq;
    cudaGetSymbolAddress((void**)&E2h,  g_E2h);
    cudaGetSymbolAddress((void**)&WTn,  g_WTn);
    cudaGetSymbolAddress((void**)&comb, g_comb);
    cudaGetSymbolAddress((void**)&h0h,  g_h0h);
    cudaGetSymbolAddress((void**)&h0t,  g_h0t);
    cudaGetSymbolAddress((void**)&h1h,  g_h1h);
    cudaGetSymbolAddress((void**)&w0t,  g_w0t);
    cudaGetSymbolAddress((void**)&w1t,  g_w1t);
    cudaGetSymbolAddress((void**)&lin,  g_lin);
    cudaGetSymbolAddress((void**)&sc0,  g_scale0);
    cudaGetSymbolAddress((void**)&sh0,  g_shift0);
    cudaGetSymbolAddress((void**)&sc1,  g_scale1);
    cudaGetSymbolAddress((void**)&sh1,  g_shift1);
    cudaGetSymbolAddress((void**)&ps,   g_ps);
    cudaGetSymbolAddress((void**)&psq,  g_psq);

    // P: all independent producers in one launch (gather blocks first)
    prep_kernel<<<GB_TOTAL, 256>>>(x, emb, lint, sw1, sw2, bilW, w0, w1,
                                   E2h, WTn, w0t, w1t, lin);
    // G1: comb = (E2 @ WTn^T) * E2 -> [p|q] scatter (fp16)
    hgemm_kernel<false, true><<<dim3(2 * BB / 128, FD / 128), 128>>>(
        E2h, WTn, comb, 2 * BB, FD, FD, nullptr, E2h);
    // G2: h0 = comb @ w0 + b0 (fp16)
    hgemm_kernel<true, false><<<dim3(BB / 128, H0N / 128), 128>>>(
        comb, w0t, h0h, BB, H0N, COMB, b0, nullptr);
    // BN0 stats (two-phase)
    bn_part_kernel<<<dim3(H0N / 64, RCH), 256>>>(h0h, H0N, ps, psq);
    bn_fin_kernel<<<H0N / 256, 256>>>(ps, psq, H0N, g0, be0, sc0, sh0);
    bnrelu_kernel<<<(BB * H0N) / 2048, 256>>>(h0h, sc0, sh0, h0t);
    // G3: h1 = h0t @ w1 + b1 (fp16)
    hgemm_kernel<true, false><<<dim3(BB / 128, H1N / 128), 128>>>(
        h0t, w1t, h1h, BB, H1N, H0N, b1, nullptr);
    // BN1 stats (two-phase)
    bn_part_kernel<<<dim3(H1N / 64, RCH), 256>>>(h1h, H1N, ps, psq);
    bn_fin_kernel<<<H1N / 256, 256>>>(ps, psq, H1N, g1, be1, sc1, sh1);
    final_kernel<<<BB / 8, 256>>>(h1h, sc1, sh1, w2, b2, lin, bias, out);
}

// round 12
// speedup vs baseline: 3.2639x; 1.0291x over previous
#include <cuda_runtime.h>
#include <cuda_fp16.h>
#include <math.h>
#include <stdint.h>

#define BB   4096
#define FF   24
#define VV   1000
#define DD   32
#define FD   768
#define COMB 1536
#define H0N  1024
#define H1N  512
#define RED  8
#define EPSV 1e-5f
#define RCH  32            // row chunks for BN partials (BB/128)

// prep mega-kernel block ranges (all 256-thread blocks)
#define GB_GATHER 4096
#define GB_TRW    (FD * FD / 256)                 // 2304
#define GB_W0     ((COMB / 32) * (H0N / 32))      // 1536
#define GB_W1     ((H0N / 32) * (H1N / 32))       // 512
#define GB_TOTAL  (GB_GATHER + GB_TRW + GB_W0 + GB_W1)

// ---------------- device scratch ----------------
__device__ __align__(16) __half g_E2h[2 * BB * FD];
__device__ __align__(16) __half g_WTn[FD * FD];
__device__ __align__(16) __half g_comb[BB * COMB];
__device__ __align__(16) __half g_h0h[BB * H0N];
__device__ __align__(16) __half g_h0t[BB * H0N];
__device__ __align__(16) __half g_h1h[BB * H1N];
__device__ __align__(16) __half g_w0t[H0N * COMB];
__device__ __align__(16) __half g_w1t[H1N * H0N];
__device__ float g_lin[BB];
__device__ float g_scale0[H0N], g_shift0[H0N];
__device__ float g_scale1[H1N], g_shift1[H1N];
__device__ __align__(16) float g_ps[RCH * H0N];   // BN partial sums
__device__ __align__(16) float g_psq[RCH * H0N];  // BN partial sumsq

__device__ __forceinline__ void cp16(unsigned dst, const void* src) {
    asm volatile("cp.async.cg.shared.global [%0], [%1], 16;" :: "r"(dst), "l"(src));
}

// ---------------- mega prep kernel -----------------------------------------
__global__ void __launch_bounds__(256)
prep_kernel(const int* __restrict__ x,
            const float* __restrict__ emb,
            const float* __restrict__ lint,
            const float* __restrict__ sw1,
            const float* __restrict__ sw2,
            const float* __restrict__ W,
            const float* __restrict__ w0,
            const float* __restrict__ w1,
            __half* __restrict__ E2h,
            __half* __restrict__ WTn,
            __half* __restrict__ w0t,
            __half* __restrict__ w1t,
            float* __restrict__ linout) {
    __shared__ union {
        float tile[32][33];
        struct {
            int   xs[FF];
            float es[FD];
            float Zs[FF], hid[RED], As[FF], linp[FF];
        } g;
    } sm;

    int blk = blockIdx.x;
    int t = threadIdx.x;

    if (blk < GB_GATHER) {
        int b = blk;
        if (t < FF) sm.g.xs[t] = x[b * FF + t];
        __syncthreads();

        #pragma unroll
        for (int r = 0; r < 3; r++) {
            int ik = t + r * 256;
            int f = ik >> 5, d = ik & 31;
            sm.g.es[ik] = emb[((long)f * VV + sm.g.xs[f]) * DD + d];
        }
        if (t < FF) sm.g.linp[t] = lint[(long)t * VV + sm.g.xs[t]];
        __syncthreads();

        int w = t >> 5, lane = t & 31;
        #pragma unroll
        for (int ff = 0; ff < 3; ff++) {
            int f = w * 3 + ff;
            float v = sm.g.es[f * 32 + lane];
            #pragma unroll
            for (int o = 16; o > 0; o >>= 1) v += __shfl_xor_sync(0xffffffffu, v, o);
            if (lane == 0) sm.g.Zs[f] = v * (1.f / 32.f);
        }
        __syncthreads();
        if (t < RED) {
            float s = 0.f;
            #pragma unroll
            for (int f = 0; f < FF; f++) s += sm.g.Zs[f] * sw1[t * FF + f];
            sm.g.hid[t] = fmaxf(s, 0.f);
        }
        __syncthreads();
        if (t < FF) {
            float s = 0.f;
            #pragma unroll
            for (int r = 0; r < RED; r++) s += sm.g.hid[r] * sw2[t * RED + r];
            sm.g.As[t] = 1.f / (1.f + expf(-s));
        }
        if (t == 0) {
            float s = 0.f;
            #pragma unroll
            for (int f = 0; f < FF; f++) s += sm.g.linp[f];
            linout[b] = s;
        }
        __syncthreads();

        #pragma unroll
        for (int r = 0; r < 3; r++) {
            int ik = t + r * 256;
            int f = ik >> 5;
            float e = sm.g.es[ik];
            E2h[(long)b * FD + ik] = __float2half_rn(e);
            E2h[(long)(BB + b) * FD + ik] = __float2half_rn(sm.g.As[f] * e);
        }
    } else if (blk < GB_GATHER + GB_TRW) {
        int o = (blk - GB_GATHER) * 256 + t;
        int jl = o % FD, ik = o / FD;
        int i = ik >> 5, k = ik & 31, j = jl >> 5, l = jl & 31;
        float v = (i == j) ? 0.f : W[(((i * FF + j) * DD + k) * DD) + l];
        WTn[o] = __float2half_rn(v);
    } else {
        const float* src;
        __half* dst;
        int K, N, kblk, nblk;
        if (blk < GB_GATHER + GB_TRW + GB_W0) {
            int idx = blk - (GB_GATHER + GB_TRW);
            src = w0; dst = w0t; K = COMB; N = H0N;
            kblk = idx % (COMB / 32); nblk = idx / (COMB / 32);
        } else {
            int idx = blk - (GB_GATHER + GB_TRW + GB_W0);
            src = w1; dst = w1t; K = H0N; N = H1N;
            kblk = idx % (H0N / 32); nblk = idx / (H0N / 32);
        }
        int k0 = kblk * 32, n0 = nblk * 32;
        int tx = t & 31, ty = t >> 5;
        #pragma unroll
        for (int j = 0; j < 4; j++)
            sm.tile[ty + j * 8][tx] = src[(long)(k0 + ty + j * 8) * N + n0 + tx];
        __syncthreads();
        #pragma unroll
        for (int j = 0; j < 4; j++)
            dst[(long)(n0 + ty + j * 8) * K + k0 + tx] =
                __float2half_rn(sm.tile[tx][ty + j * 8]);
    }
}

// ---------------- fp16 GEMM: ldmatrix + m16n8k16 + cp.async 4-stage --------
// BNPART: epilogue also emits per-block column sum/sumsq partials
// (chunk = blockIdx.x) into ps/psq — replaces the bn_part pass.
template <bool BIAS, bool COMBINE, bool BNPART>
__global__ void __launch_bounds__(128, 2)
hgemm_kernel(const __half* __restrict__ A, const __half* __restrict__ Bt,
             __half* __restrict__ C, int M, int N, int K,
             const float* __restrict__ bias, const __half* __restrict__ E2,
             float* __restrict__ ps, float* __restrict__ psq) {
    __shared__ __align__(16) __half Asm[4][2048];
    __shared__ __align__(16) __half Bsm[4][2048];
    __shared__ float bred_s[4][64], bred_q[4][64];
    int t = threadIdx.x;
    int m0 = blockIdx.x * 128, n0 = blockIdx.y * 128;
    int wid = t >> 5, lane = t & 31;
    int wm = (wid & 1) * 64, wn = (wid >> 1) * 64;
    int r = lane >> 2, quad = lane & 3;

    float acc[4][8][4];
    #pragma unroll
    for (int mi = 0; mi < 4; mi++)
        #pragma unroll
        for (int ni = 0; ni < 8; ni++)
            #pragma unroll
            for (int c = 0; c < 4; c++) acc[mi][ni][c] = 0.f;

    int srow = t >> 1, sc = t & 1;
    const __half* Ap = A + (long)(m0 + srow) * K + sc * 8;
    const __half* Bp = Bt + (long)(n0 + srow) * K + sc * 8;
    int swz = (srow >> 2) & 1;
    unsigned off0 = (unsigned)(srow * 16 + ((sc ^ swz) << 3)) * 2u;
    unsigned off1 = (unsigned)((srow + 64) * 16 + ((sc ^ swz) << 3)) * 2u;

    unsigned abase = (unsigned)__cvta_generic_to_shared(Asm[0]);
    unsigned bbase = (unsigned)__cvta_generic_to_shared(Bsm[0]);

    unsigned aaddr[4], baddr[4];
    #pragma unroll
    for (int mi = 0; mi < 4; mi++) {
        int row = wm + mi * 16 + (lane & 7) + ((lane >> 3) & 1) * 8;
        int kc  = (lane >> 4) & 1;
        aaddr[mi] = abase + (unsigned)(row * 16 + ((kc ^ ((row >> 2) & 1)) << 3)) * 2u;
    }
    #pragma unroll
    for (int np = 0; np < 4; np++) {
        int row = wn + np * 16 + (lane & 7) + ((lane >> 4) & 1) * 8;
        int kc  = (lane >> 3) & 1;
        baddr[np] = bbase + (unsigned)(row * 16 + ((kc ^ ((row >> 2) & 1)) << 3)) * 2u;
    }

    int nt = K >> 4;
    long rstep = 64 * (long)K;

    #define STAGE(i)                                                        \
        do {                                                                \
            if ((i) < nt) {                                                 \
                unsigned bo = (unsigned)((i) & 3) * 4096u;                  \
                const __half* ak = Ap + (i) * 16;                           \
                const __half* bk = Bp + (i) * 16;                           \
                cp16(abase + bo + off0, ak);                                \
                cp16(abase + bo + off1, ak + rstep);                        \
                cp16(bbase + bo + off0, bk);                                \
                cp16(bbase + bo + off1, bk + rstep);                        \
            }                                                               \
            asm volatile("cp.async.commit_group;");                         \
        } while (0)

    STAGE(0); STAGE(1); STAGE(2);

    for (int i = 0; i < nt; i++) {
        asm volatile("cp.async.wait_group 2;");
        __syncthreads();
        unsigned boff = (unsigned)(i & 3) * 4096u;
        unsigned af[4][4], bf[4][4];
        #pragma unroll
        for (int mi = 0; mi < 4; mi++)
            asm volatile("ldmatrix.sync.aligned.m8n8.x4.shared.b16 {%0,%1,%2,%3}, [%4];"
                : "=r"(af[mi][0]), "=r"(af[mi][1]), "=r"(af[mi][2]), "=r"(af[mi][3])
                : "r"(aaddr[mi] + boff));
        #pragma unroll
        for (int np = 0; np < 4; np++)
            asm volatile("ldmatrix.sync.aligned.m8n8.x4.shared.b16 {%0,%1,%2,%3}, [%4];"
                : "=r"(bf[np][0]), "=r"(bf[np][1]), "=r"(bf[np][2]), "=r"(bf[np][3])
                : "r"(baddr[np] + boff));
        #pragma unroll
        for (int mi = 0; mi < 4; mi++)
            #pragma unroll
            for (int ni = 0; ni < 8; ni++) {
                asm volatile(
                    "mma.sync.aligned.m16n8k16.row.col.f32.f16.f16.f32 "
                    "{%0,%1,%2,%3}, {%4,%5,%6,%7}, {%8,%9}, {%0,%1,%2,%3};"
                    : "+f"(acc[mi][ni][0]), "+f"(acc[mi][ni][1]),
                      "+f"(acc[mi][ni][2]), "+f"(acc[mi][ni][3])
                    : "r"(af[mi][0]), "r"(af[mi][1]), "r"(af[mi][2]), "r"(af[mi][3]),
                      "r"(bf[ni >> 1][(ni & 1) * 2]), "r"(bf[ni >> 1][(ni & 1) * 2 + 1]));
            }
        STAGE(i + 3);
    }
    #undef STAGE
    asm volatile("cp.async.wait_group 0;");

    float cs[8][2], cq[8][2];
    if (BNPART) {
        #pragma unroll
        for (int ni = 0; ni < 8; ni++) {
            cs[ni][0] = cs[ni][1] = 0.f;
            cq[ni][0] = cq[ni][1] = 0.f;
        }
    }

    #pragma unroll
    for (int mi = 0; mi < 4; mi++) {
        #pragma unroll
        for (int ni = 0; ni < 8; ni++) {
            int row0 = m0 + wm + mi * 16 + r;
            int row1 = row0 + 8;
            int col  = n0 + wn + ni * 8 + 2 * quad;
            float2 v0 = make_float2(acc[mi][ni][0], acc[mi][ni][1]);
            float2 v1 = make_float2(acc[mi][ni][2], acc[mi][ni][3]);
            if (BIAS) {
                float b0v = bias[col], b1v = bias[col + 1];
                v0.x += b0v; v0.y += b1v;
                v1.x += b0v; v1.y += b1v;
            }
            if (COMBINE) {
                float2 e0 = __half22float2(*(const __half2*)&E2[(long)row0 * FD + col]);
                float2 e1 = __half22float2(*(const __half2*)&E2[(long)row1 * FD + col]);
                v0.x *= e0.x; v0.y *= e0.y;
                v1.x *= e1.x; v1.y *= e1.y;
                long br0 = (row0 < BB) ? row0 : (row0 - BB);
                long br1 = (row1 < BB) ? row1 : (row1 - BB);
                int  c0  = (row0 < BB) ? 0 : FD;
                int  c1  = (row1 < BB) ? 0 : FD;
                *(__half2*)&C[br0 * (long)COMB + c0 + col] = __floats2half2_rn(v0.x, v0.y);
                *(__half2*)&C[br1 * (long)COMB + c1 + col] = __floats2half2_rn(v1.x, v1.y);
            } else {
                __half2 h0 = __floats2half2_rn(v0.x, v0.y);
                __half2 h1 = __floats2half2_rn(v1.x, v1.y);
                *(__half2*)&C[(long)row0 * N + col] = h0;
                *(__half2*)&C[(long)row1 * N + col] = h1;
                if (BNPART) {
                    float2 f0 = __half22float2(h0), f1 = __half22float2(h1);
                    cs[ni][0] += f0.x + f1.x;
                    cs[ni][1] += f0.y + f1.y;
                    cq[ni][0] += f0.x * f0.x + f1.x * f1.x;
                    cq[ni][1] += f0.y * f0.y + f1.y * f1.y;
                }
            }
        }
    }

    if (BNPART) {
        // reduce over r within the warp (xor 4/8/16 preserves quad => same column)
        #pragma unroll
        for (int ni = 0; ni < 8; ni++)
            #pragma unroll
            for (int j = 0; j < 2; j++) {
                #pragma unroll
                for (int d = 4; d <= 16; d <<= 1) {
                    cs[ni][j] += __shfl_xor_sync(0xffffffffu, cs[ni][j], d);
                    cq[ni][j] += __shfl_xor_sync(0xffffffffu, cq[ni][j], d);
                }
            }
        if (lane < 4) {
            #pragma unroll
            for (int ni = 0; ni < 8; ni++) {
                bred_s[wid][ni * 8 + 2 * lane + 0] = cs[ni][0];
                bred_s[wid][ni * 8 + 2 * lane + 1] = cs[ni][1];
                bred_q[wid][ni * 8 + 2 * lane + 0] = cq[ni][0];
                bred_q[wid][ni * 8 + 2 * lane + 1] = cq[ni][1];
            }
        }
        __syncthreads();
        if ((wid & 1) == 0) {
            int base = n0 + (wid >> 1) * 64;
            #pragma unroll
            for (int c = lane; c < 64; c += 32) {
                float s = bred_s[wid][c] + bred_s[wid | 1][c];
                float q = bred_q[wid][c] + bred_q[wid | 1][c];
                ps[(long)blockIdx.x * N + base + c]  = s;
                psq[(long)blockIdx.x * N + base + c] = q;
            }
        }
    }
}

// ---------------- BN finalize -> scale/shift -------------------------------
__global__ void __launch_bounds__(256)
bn_fin_kernel(const float* __restrict__ ps, const float* __restrict__ psq, int N,
              const float* __restrict__ g, const float* __restrict__ be,
              float* __restrict__ scale, float* __restrict__ shift) {
    int col = blockIdx.x * 256 + threadIdx.x;
    float s = 0.f, q = 0.f;
    #pragma unroll
    for (int i = 0; i < RCH; i++) {
        s += ps[(long)i * N + col];
        q += psq[(long)i * N + col];
    }
    float mean = s * (1.f / BB);
    float var  = q * (1.f / BB) - mean * mean;
    float sc   = g[col] * rsqrtf(var + EPSV);
    scale[col] = sc;
    shift[col] = be[col] - mean * sc;
}

// ---------------- relu(bn(h0)) fp16 -> fp16 --------------------------------
__global__ void bnrelu_kernel(const __half* __restrict__ H,
                              const float* __restrict__ scale,
                              const float* __restrict__ shift,
                              __half* __restrict__ Ht) {
    int i = (blockIdx.x * 256 + threadIdx.x) * 8;
    int col = i & (H0N - 1);
    uint4 raw = *(const uint4*)&H[i];
    const __half2* hp = (const __half2*)&raw;
    uint4 outw;
    __half2* op = (__half2*)&outw;
    #pragma unroll
    for (int j = 0; j < 4; j++) {
        float2 v = __half22float2(hp[j]);
        float a = fmaxf(0.f, v.x * scale[col + 2 * j] + shift[col + 2 * j]);
        float b = fmaxf(0.f, v.y * scale[col + 2 * j + 1] + shift[col + 2 * j + 1]);
        op[j] = __floats2half2_rn(a, b);
    }
    *(uint4*)&Ht[i] = outw;
}

// ---------------- final ----------------------------------------------------
__global__ void final_kernel(const __half* __restrict__ H1,
                             const float* __restrict__ scale, const float* __restrict__ shift,
                             const float* __restrict__ w2, const float* __restrict__ b2,
                             const float* __restrict__ lin, const float* __restrict__ bias0,
                             float* __restrict__ out) {
    int warp = threadIdx.x >> 5, lane = threadIdx.x & 31;
    int row = blockIdx.x * 8 + warp;
    float acc = 0.f;
    #pragma unroll 4
    for (int k = lane * 2; k < H1N; k += 64) {
        float2 v = __half22float2(*(const __half2*)&H1[(long)row * H1N + k]);
        float a = fmaxf(0.f, v.x * scale[k] + shift[k]);
        float b = fmaxf(0.f, v.y * scale[k + 1] + shift[k + 1]);
        acc += a * w2[k] + b * w2[k + 1];
    }
    #pragma unroll
    for (int o = 16; o > 0; o >>= 1) acc += __shfl_xor_sync(0xffffffffu, acc, o);
    if (lane == 0) {
        float logit = acc + b2[0] + lin[row] + bias0[0];
        out[row] = 1.f / (1.f + expf(-logit));
    }
}

// ---------------------------------------------------------------------------
extern "C" void kernel_launch(void* const* d_in, const int* in_sizes, int n_in,
                              void* d_out, int out_size) {
    const int*   x    = (const int*)d_in[0];
    const float* emb  = (const float*)d_in[1];
    const float* lint = (const float*)d_in[2];
    const float* bias = (const float*)d_in[3];
    const float* sw1  = (const float*)d_in[4];
    const float* sw2  = (const float*)d_in[5];
    const float* bilW = (const float*)d_in[6];
    const float* w0   = (const float*)d_in[7];
    const float* b0   = (const float*)d_in[8];
    const float* g0   = (const float*)d_in[9];
    const float* be0  = (const float*)d_in[10];
    const float* w1   = (const float*)d_in[11];
    const float* b1   = (const float*)d_in[12];
    const float* g1   = (const float*)d_in[13];
    const float* be1  = (const float*)d_in[14];
    const float* w2   = (const float*)d_in[15];
    const float* b2   = (const float*)d_in[16];
    float* out = (float*)d_out;

    __half *E2h, *WTn, *comb, *h0h, *h0t, *h1h, *w0t, *w1t;
    float *lin, *sc0, *sh0, *sc1, *sh1, *ps, *psq;
    cudaGetSymbolAddress((void**)&E2h,  g_E2h);
    cudaGetSymbolAddress((void**)&WTn,  g_WTn);
    cudaGetSymbolAddress((void**)&comb, g_comb);
    cudaGetSymbolAddress((void**)&h0h,  g_h0h);
    cudaGetSymbolAddress((void**)&h0t,  g_h0t);
    cudaGetSymbolAddress((void**)&h1h,  g_h1h);
    cudaGetSymbolAddress((void**)&w0t,  g_w0t);
    cudaGetSymbolAddress((void**)&w1t,  g_w1t);
    cudaGetSymbolAddress((void**)&lin,  g_lin);
    cudaGetSymbolAddress((void**)&sc0,  g_scale0);
    cudaGetSymbolAddress((void**)&sh0,  g_shift0);
    cudaGetSymbolAddress((void**)&sc1,  g_scale1);
    cudaGetSymbolAddress((void**)&sh1,  g_shift1);
    cudaGetSymbolAddress((void**)&ps,   g_ps);
    cudaGetSymbolAddress((void**)&psq,  g_psq);

    // P: all independent producers in one launch (gather blocks first)
    prep_kernel<<<GB_TOTAL, 256>>>(x, emb, lint, sw1, sw2, bilW, w0, w1,
                                   E2h, WTn, w0t, w1t, lin);
    // G1: comb = (E2 @ WTn^T) * E2 -> [p|q] scatter (fp16)
    hgemm_kernel<false, true, false><<<dim3(2 * BB / 128, FD / 128), 128>>>(
        E2h, WTn, comb, 2 * BB, FD, FD, nullptr, E2h, nullptr, nullptr);
    // G2: h0 = comb @ w0 + b0 (fp16) + fused BN partials
    hgemm_kernel<true, false, true><<<dim3(BB / 128, H0N / 128), 128>>>(
        comb, w0t, h0h, BB, H0N, COMB, b0, nullptr, ps, psq);
    bn_fin_kernel<<<H0N / 256, 256>>>(ps, psq, H0N, g0, be0, sc0, sh0);
    bnrelu_kernel<<<(BB * H0N) / 2048, 256>>>(h0h, sc0, sh0, h0t);
    // G3: h1 = h0t @ w1 + b1 (fp16) + fused BN partials
    hgemm_kernel<true, false, true><<<dim3(BB / 128, H1N / 128), 128>>>(
        h0t, w1t, h1h, BB, H1N, H0N, b1, nullptr, ps, psq);
    bn_fin_kernel<<<H1N / 256, 256>>>(ps, psq, H1N, g1, be1, sc1, sh1);
    final_kernel<<<BB / 8, 256>>>(h1h, sc1, sh1, w2, b2, lin, bias, out);
}

// round 13
// speedup vs baseline: 3.3154x; 1.0158x over previous
#include <cuda_runtime.h>
#include <cuda_fp16.h>
#include <math.h>
#include <stdint.h>

#define BB   4096
#define FF   24
#define VV   1000
#define DD   32
#define FD   768
#define COMB 1536
#define H0N  1024
#define H1N  512
#define RED  8
#define EPSV 1e-5f
#define RCH  32            // row chunks for BN partials (BB/128)

// prep mega-kernel block ranges (all 256-thread blocks)
#define GB_GATHER 4096
#define GB_TRW    (FD * FD / 256)                 // 2304
#define GB_W0     ((COMB / 32) * (H0N / 32))      // 1536
#define GB_W1     ((H0N / 32) * (H1N / 32))       // 512
#define GB_TOTAL  (GB_GATHER + GB_TRW + GB_W0 + GB_W1)

// ---------------- device scratch ----------------
__device__ __align__(16) __half g_E2h[2 * BB * FD];
__device__ __align__(16) __half g_WTn[FD * FD];
__device__ __align__(16) __half g_comb[BB * COMB];
__device__ __align__(16) __half g_h0h[BB * H0N];
__device__ __align__(16) __half g_h0t[BB * H0N];
__device__ __align__(16) __half g_h1h[BB * H1N];
__device__ __align__(16) __half g_w0t[H0N * COMB];
__device__ __align__(16) __half g_w1t[H1N * H0N];
__device__ float g_lin[BB];
__device__ float g_scale0[H0N], g_shift0[H0N];
__device__ float g_scale1[H1N], g_shift1[H1N];
__device__ __align__(16) float g_ps[RCH * H0N];   // BN partial sums
__device__ __align__(16) float g_psq[RCH * H0N];  // BN partial sumsq

__device__ __forceinline__ void cp16(unsigned dst, const void* src) {
    asm volatile("cp.async.cg.shared.global [%0], [%1], 16;" :: "r"(dst), "l"(src));
}

// ---------------- mega prep kernel -----------------------------------------
__global__ void __launch_bounds__(256)
prep_kernel(const int* __restrict__ x,
            const float* __restrict__ emb,
            const float* __restrict__ lint,
            const float* __restrict__ sw1,
            const float* __restrict__ sw2,
            const float* __restrict__ W,
            const float* __restrict__ w0,
            const float* __restrict__ w1,
            __half* __restrict__ E2h,
            __half* __restrict__ WTn,
            __half* __restrict__ w0t,
            __half* __restrict__ w1t,
            float* __restrict__ linout) {
    __shared__ union {
        float tile[32][33];
        struct {
            int   xs[FF];
            float es[FD];
            float Zs[FF], hid[RED], As[FF], linp[FF];
        } g;
    } sm;

    int blk = blockIdx.x;
    int t = threadIdx.x;

    if (blk < GB_GATHER) {
        int b = blk;
        if (t < FF) sm.g.xs[t] = x[b * FF + t];
        __syncthreads();

        #pragma unroll
        for (int r = 0; r < 3; r++) {
            int ik = t + r * 256;
            int f = ik >> 5, d = ik & 31;
            sm.g.es[ik] = emb[((long)f * VV + sm.g.xs[f]) * DD + d];
        }
        if (t < FF) sm.g.linp[t] = lint[(long)t * VV + sm.g.xs[t]];
        __syncthreads();

        int w = t >> 5, lane = t & 31;
        #pragma unroll
        for (int ff = 0; ff < 3; ff++) {
            int f = w * 3 + ff;
            float v = sm.g.es[f * 32 + lane];
            #pragma unroll
            for (int o = 16; o > 0; o >>= 1) v += __shfl_xor_sync(0xffffffffu, v, o);
            if (lane == 0) sm.g.Zs[f] = v * (1.f / 32.f);
        }
        __syncthreads();
        if (t < RED) {
            float s = 0.f;
            #pragma unroll
            for (int f = 0; f < FF; f++) s += sm.g.Zs[f] * sw1[t * FF + f];
            sm.g.hid[t] = fmaxf(s, 0.f);
        }
        __syncthreads();
        if (t < FF) {
            float s = 0.f;
            #pragma unroll
            for (int r = 0; r < RED; r++) s += sm.g.hid[r] * sw2[t * RED + r];
            sm.g.As[t] = 1.f / (1.f + expf(-s));
        }
        if (t == 0) {
            float s = 0.f;
            #pragma unroll
            for (int f = 0; f < FF; f++) s += sm.g.linp[f];
            linout[b] = s;
        }
        __syncthreads();

        #pragma unroll
        for (int r = 0; r < 3; r++) {
            int ik = t + r * 256;
            int f = ik >> 5;
            float e = sm.g.es[ik];
            E2h[(long)b * FD + ik] = __float2half_rn(e);
            E2h[(long)(BB + b) * FD + ik] = __float2half_rn(sm.g.As[f] * e);
        }
    } else if (blk < GB_GATHER + GB_TRW) {
        int o = (blk - GB_GATHER) * 256 + t;
        int jl = o % FD, ik = o / FD;
        int i = ik >> 5, k = ik & 31, j = jl >> 5, l = jl & 31;
        float v = (i == j) ? 0.f : W[(((i * FF + j) * DD + k) * DD) + l];
        WTn[o] = __float2half_rn(v);
    } else {
        const float* src;
        __half* dst;
        int K, N, kblk, nblk;
        if (blk < GB_GATHER + GB_TRW + GB_W0) {
            int idx = blk - (GB_GATHER + GB_TRW);
            src = w0; dst = w0t; K = COMB; N = H0N;
            kblk = idx % (COMB / 32); nblk = idx / (COMB / 32);
        } else {
            int idx = blk - (GB_GATHER + GB_TRW + GB_W0);
            src = w1; dst = w1t; K = H0N; N = H1N;
            kblk = idx % (H0N / 32); nblk = idx / (H0N / 32);
        }
        int k0 = kblk * 32, n0 = nblk * 32;
        int tx = t & 31, ty = t >> 5;
        #pragma unroll
        for (int j = 0; j < 4; j++)
            sm.tile[ty + j * 8][tx] = src[(long)(k0 + ty + j * 8) * N + n0 + tx];
        __syncthreads();
        #pragma unroll
        for (int j = 0; j < 4; j++)
            dst[(long)(n0 + ty + j * 8) * K + k0 + tx] =
                __float2half_rn(sm.tile[tx][ty + j * 8]);
    }
}

// ---------------- fp16 GEMM: ldmatrix + m16n8k16 + cp.async 4-stage --------
// BNPART: epilogue also emits per-block column sum/sumsq partials
// (chunk = blockIdx.x) into ps/psq.
template <bool BIAS, bool COMBINE, bool BNPART>
__global__ void __launch_bounds__(128, 2)
hgemm_kernel(const __half* __restrict__ A, const __half* __restrict__ Bt,
             __half* __restrict__ C, int M, int N, int K,
             const float* __restrict__ bias, const __half* __restrict__ E2,
             float* __restrict__ ps, float* __restrict__ psq) {
    __shared__ __align__(16) __half Asm[4][2048];
    __shared__ __align__(16) __half Bsm[4][2048];
    __shared__ float bred_s[4][64], bred_q[4][64];
    int t = threadIdx.x;
    int m0 = blockIdx.x * 128, n0 = blockIdx.y * 128;
    int wid = t >> 5, lane = t & 31;
    int wm = (wid & 1) * 64, wn = (wid >> 1) * 64;
    int r = lane >> 2, quad = lane & 3;

    float acc[4][8][4];
    #pragma unroll
    for (int mi = 0; mi < 4; mi++)
        #pragma unroll
        for (int ni = 0; ni < 8; ni++)
            #pragma unroll
            for (int c = 0; c < 4; c++) acc[mi][ni][c] = 0.f;

    int srow = t >> 1, sc = t & 1;
    const __half* Ap = A + (long)(m0 + srow) * K + sc * 8;
    const __half* Bp = Bt + (long)(n0 + srow) * K + sc * 8;
    int swz = (srow >> 2) & 1;
    unsigned off0 = (unsigned)(srow * 16 + ((sc ^ swz) << 3)) * 2u;
    unsigned off1 = (unsigned)((srow + 64) * 16 + ((sc ^ swz) << 3)) * 2u;

    unsigned abase = (unsigned)__cvta_generic_to_shared(Asm[0]);
    unsigned bbase = (unsigned)__cvta_generic_to_shared(Bsm[0]);

    unsigned aaddr[4], baddr[4];
    #pragma unroll
    for (int mi = 0; mi < 4; mi++) {
        int row = wm + mi * 16 + (lane & 7) + ((lane >> 3) & 1) * 8;
        int kc  = (lane >> 4) & 1;
        aaddr[mi] = abase + (unsigned)(row * 16 + ((kc ^ ((row >> 2) & 1)) << 3)) * 2u;
    }
    #pragma unroll
    for (int np = 0; np < 4; np++) {
        int row = wn + np * 16 + (lane & 7) + ((lane >> 4) & 1) * 8;
        int kc  = (lane >> 3) & 1;
        baddr[np] = bbase + (unsigned)(row * 16 + ((kc ^ ((row >> 2) & 1)) << 3)) * 2u;
    }

    int nt = K >> 4;
    long rstep = 64 * (long)K;

    #define STAGE(i)                                                        \
        do {                                                                \
            if ((i) < nt) {                                                 \
                unsigned bo = (unsigned)((i) & 3) * 4096u;                  \
                const __half* ak = Ap + (i) * 16;                           \
                const __half* bk = Bp + (i) * 16;                           \
                cp16(abase + bo + off0, ak);                                \
                cp16(abase + bo + off1, ak + rstep);                        \
                cp16(bbase + bo + off0, bk);                                \
                cp16(bbase + bo + off1, bk + rstep);                        \
            }                                                               \
            asm volatile("cp.async.commit_group;");                         \
        } while (0)

    STAGE(0); STAGE(1); STAGE(2);

    for (int i = 0; i < nt; i++) {
        asm volatile("cp.async.wait_group 2;");
        __syncthreads();
        unsigned boff = (unsigned)(i & 3) * 4096u;
        unsigned af[4][4], bf[4][4];
        #pragma unroll
        for (int mi = 0; mi < 4; mi++)
            asm volatile("ldmatrix.sync.aligned.m8n8.x4.shared.b16 {%0,%1,%2,%3}, [%4];"
                : "=r"(af[mi][0]), "=r"(af[mi][1]), "=r"(af[mi][2]), "=r"(af[mi][3])
                : "r"(aaddr[mi] + boff));
        #pragma unroll
        for (int np = 0; np < 4; np++)
            asm volatile("ldmatrix.sync.aligned.m8n8.x4.shared.b16 {%0,%1,%2,%3}, [%4];"
                : "=r"(bf[np][0]), "=r"(bf[np][1]), "=r"(bf[np][2]), "=r"(bf[np][3])
                : "r"(baddr[np] + boff));
        #pragma unroll
        for (int mi = 0; mi < 4; mi++)
            #pragma unroll
            for (int ni = 0; ni < 8; ni++) {
                asm volatile(
                    "mma.sync.aligned.m16n8k16.row.col.f32.f16.f16.f32 "
                    "{%0,%1,%2,%3}, {%4,%5,%6,%7}, {%8,%9}, {%0,%1,%2,%3};"
                    : "+f"(acc[mi][ni][0]), "+f"(acc[mi][ni][1]),
                      "+f"(acc[mi][ni][2]), "+f"(acc[mi][ni][3])
                    : "r"(af[mi][0]), "r"(af[mi][1]), "r"(af[mi][2]), "r"(af[mi][3]),
                      "r"(bf[ni >> 1][(ni & 1) * 2]), "r"(bf[ni >> 1][(ni & 1) * 2 + 1]));
            }
        STAGE(i + 3);
    }
    #undef STAGE
    asm volatile("cp.async.wait_group 0;");

    float cs[8][2], cq[8][2];
    if (BNPART) {
        #pragma unroll
        for (int ni = 0; ni < 8; ni++) {
            cs[ni][0] = cs[ni][1] = 0.f;
            cq[ni][0] = cq[ni][1] = 0.f;
        }
    }

    #pragma unroll
    for (int mi = 0; mi < 4; mi++) {
        #pragma unroll
        for (int ni = 0; ni < 8; ni++) {
            int row0 = m0 + wm + mi * 16 + r;
            int row1 = row0 + 8;
            int col  = n0 + wn + ni * 8 + 2 * quad;
            float2 v0 = make_float2(acc[mi][ni][0], acc[mi][ni][1]);
            float2 v1 = make_float2(acc[mi][ni][2], acc[mi][ni][3]);
            if (BIAS) {
                float b0v = bias[col], b1v = bias[col + 1];
                v0.x += b0v; v0.y += b1v;
                v1.x += b0v; v1.y += b1v;
            }
            if (COMBINE) {
                float2 e0 = __half22float2(*(const __half2*)&E2[(long)row0 * FD + col]);
                float2 e1 = __half22float2(*(const __half2*)&E2[(long)row1 * FD + col]);
                v0.x *= e0.x; v0.y *= e0.y;
                v1.x *= e1.x; v1.y *= e1.y;
                long br0 = (row0 < BB) ? row0 : (row0 - BB);
                long br1 = (row1 < BB) ? row1 : (row1 - BB);
                int  c0  = (row0 < BB) ? 0 : FD;
                int  c1  = (row1 < BB) ? 0 : FD;
                *(__half2*)&C[br0 * (long)COMB + c0 + col] = __floats2half2_rn(v0.x, v0.y);
                *(__half2*)&C[br1 * (long)COMB + c1 + col] = __floats2half2_rn(v1.x, v1.y);
            } else {
                __half2 h0 = __floats2half2_rn(v0.x, v0.y);
                __half2 h1 = __floats2half2_rn(v1.x, v1.y);
                *(__half2*)&C[(long)row0 * N + col] = h0;
                *(__half2*)&C[(long)row1 * N + col] = h1;
                if (BNPART) {
                    float2 f0 = __half22float2(h0), f1 = __half22float2(h1);
                    cs[ni][0] += f0.x + f1.x;
                    cs[ni][1] += f0.y + f1.y;
                    cq[ni][0] += f0.x * f0.x + f1.x * f1.x;
                    cq[ni][1] += f0.y * f0.y + f1.y * f1.y;
                }
            }
        }
    }

    if (BNPART) {
        #pragma unroll
        for (int ni = 0; ni < 8; ni++)
            #pragma unroll
            for (int j = 0; j < 2; j++) {
                #pragma unroll
                for (int d = 4; d <= 16; d <<= 1) {
                    cs[ni][j] += __shfl_xor_sync(0xffffffffu, cs[ni][j], d);
                    cq[ni][j] += __shfl_xor_sync(0xffffffffu, cq[ni][j], d);
                }
            }
        if (lane < 4) {
            #pragma unroll
            for (int ni = 0; ni < 8; ni++) {
                bred_s[wid][ni * 8 + 2 * lane + 0] = cs[ni][0];
                bred_s[wid][ni * 8 + 2 * lane + 1] = cs[ni][1];
                bred_q[wid][ni * 8 + 2 * lane + 0] = cq[ni][0];
                bred_q[wid][ni * 8 + 2 * lane + 1] = cq[ni][1];
            }
        }
        __syncthreads();
        if ((wid & 1) == 0) {
            int base = n0 + (wid >> 1) * 64;
            #pragma unroll
            for (int c = lane; c < 64; c += 32) {
                float s = bred_s[wid][c] + bred_s[wid | 1][c];
                float q = bred_q[wid][c] + bred_q[wid | 1][c];
                ps[(long)blockIdx.x * N + base + c]  = s;
                psq[(long)blockIdx.x * N + base + c] = q;
            }
        }
    }
}

// ---------------- BN finalize -> scale/shift -------------------------------
// block = 32 cols x 8 chunk-groups (each thread sums 4 partials); grid = N/32.
__global__ void __launch_bounds__(256)
bn_fin_kernel(const float* __restrict__ ps, const float* __restrict__ psq, int N,
              const float* __restrict__ g, const float* __restrict__ be,
              float* __restrict__ scale, float* __restrict__ shift) {
    int lane = threadIdx.x & 31;
    int part = threadIdx.x >> 5;                   // 0..7
    int col  = blockIdx.x * 32 + lane;
    float s = 0.f, q = 0.f;
    #pragma unroll
    for (int i = 0; i < 4; i++) {
        long o = (long)(part * 4 + i) * N + col;
        s += ps[o];
        q += psq[o];
    }
    __shared__ float sm_s[8][32], sm_q[8][32];
    sm_s[part][lane] = s; sm_q[part][lane] = q;
    __syncthreads();
    if (part == 0) {
        #pragma unroll
        for (int i = 1; i < 8; i++) { s += sm_s[i][lane]; q += sm_q[i][lane]; }
        float mean = s * (1.f / BB);
        float var  = q * (1.f / BB) - mean * mean;
        float sc   = g[col] * rsqrtf(var + EPSV);
        scale[col] = sc;
        shift[col] = be[col] - mean * sc;
    }
}

// ---------------- relu(bn(h0)) fp16 -> fp16 --------------------------------
__global__ void bnrelu_kernel(const __half* __restrict__ H,
                              const float* __restrict__ scale,
                              const float* __restrict__ shift,
                              __half* __restrict__ Ht) {
    int i = (blockIdx.x * 256 + threadIdx.x) * 8;
    int col = i & (H0N - 1);
    uint4 raw = *(const uint4*)&H[i];
    const __half2* hp = (const __half2*)&raw;
    uint4 outw;
    __half2* op = (__half2*)&outw;
    #pragma unroll
    for (int j = 0; j < 4; j++) {
        float2 v = __half22float2(hp[j]);
        float a = fmaxf(0.f, v.x * scale[col + 2 * j] + shift[col + 2 * j]);
        float b = fmaxf(0.f, v.y * scale[col + 2 * j + 1] + shift[col + 2 * j + 1]);
        op[j] = __floats2half2_rn(a, b);
    }
    *(uint4*)&Ht[i] = outw;
}

// ---------------- final ----------------------------------------------------
__global__ void final_kernel(const __half* __restrict__ H1,
                             const float* __restrict__ scale, const float* __restrict__ shift,
                             const float* __restrict__ w2, const float* __restrict__ b2,
                             const float* __restrict__ lin, const float* __restrict__ bias0,
                             float* __restrict__ out) {
    int warp = threadIdx.x >> 5, lane = threadIdx.x & 31;
    int row = blockIdx.x * 8 + warp;
    float acc = 0.f;
    #pragma unroll 4
    for (int k = lane * 2; k < H1N; k += 64) {
        float2 v = __half22float2(*(const __half2*)&H1[(long)row * H1N + k]);
        float a = fmaxf(0.f, v.x * scale[k] + shift[k]);
        float b = fmaxf(0.f, v.y * scale[k + 1] + shift[k + 1]);
        acc += a * w2[k] + b * w2[k + 1];
    }
    #pragma unroll
    for (int o = 16; o > 0; o >>= 1) acc += __shfl_xor_sync(0xffffffffu, acc, o);
    if (lane == 0) {
        float logit = acc + b2[0] + lin[row] + bias0[0];
        out[row] = 1.f / (1.f + expf(-logit));
    }
}

// ---------------------------------------------------------------------------
extern "C" void kernel_launch(void* const* d_in, const int* in_sizes, int n_in,
                              void* d_out, int out_size) {
    const int*   x    = (const int*)d_in[0];
    const float* emb  = (const float*)d_in[1];
    const float* lint = (const float*)d_in[2];
    const float* bias = (const float*)d_in[3];
    const float* sw1  = (const float*)d_in[4];
    const float* sw2  = (const float*)d_in[5];
    const float* bilW = (const float*)d_in[6];
    const float* w0   = (const float*)d_in[7];
    const float* b0   = (const float*)d_in[8];
    const float* g0   = (const float*)d_in[9];
    const float* be0  = (const float*)d_in[10];
    const float* w1   = (const float*)d_in[11];
    const float* b1   = (const float*)d_in[12];
    const float* g1   = (const float*)d_in[13];
    const float* be1  = (const float*)d_in[14];
    const float* w2   = (const float*)d_in[15];
    const float* b2   = (const float*)d_in[16];
    float* out = (float*)d_out;

    __half *E2h, *WTn, *comb, *h0h, *h0t, *h1h, *w0t, *w1t;
    float *lin, *sc0, *sh0, *sc1, *sh1, *ps, *psq;
    cudaGetSymbolAddress((void**)&E2h,  g_E2h);
    cudaGetSymbolAddress((void**)&WTn,  g_WTn);
    cudaGetSymbolAddress((void**)&comb, g_comb);
    cudaGetSymbolAddress((void**)&h0h,  g_h0h);
    cudaGetSymbolAddress((void**)&h0t,  g_h0t);
    cudaGetSymbolAddress((void**)&h1h,  g_h1h);
    cudaGetSymbolAddress((void**)&w0t,  g_w0t);
    cudaGetSymbolAddress((void**)&w1t,  g_w1t);
    cudaGetSymbolAddress((void**)&lin,  g_lin);
    cudaGetSymbolAddress((void**)&sc0,  g_scale0);
    cudaGetSymbolAddress((void**)&sh0,  g_shift0);
    cudaGetSymbolAddress((void**)&sc1,  g_scale1);
    cudaGetSymbolAddress((void**)&sh1,  g_shift1);
    cudaGetSymbolAddress((void**)&ps,   g_ps);
    cudaGetSymbolAddress((void**)&psq,  g_psq);

    // P: all independent producers in one launch (gather blocks first)
    prep_kernel<<<GB_TOTAL, 256>>>(x, emb, lint, sw1, sw2, bilW, w0, w1,
                                   E2h, WTn, w0t, w1t, lin);
    // G1: comb = (E2 @ WTn^T) * E2 -> [p|q] scatter (fp16)
    hgemm_kernel<false, true, false><<<dim3(2 * BB / 128, FD / 128), 128>>>(
        E2h, WTn, comb, 2 * BB, FD, FD, nullptr, E2h, nullptr, nullptr);
    // G2: h0 = comb @ w0 + b0 (fp16) + fused BN partials
    hgemm_kernel<true, false, true><<<dim3(BB / 128, H0N / 128), 128>>>(
        comb, w0t, h0h, BB, H0N, COMB, b0, nullptr, ps, psq);
    bn_fin_kernel<<<H0N / 32, 256>>>(ps, psq, H0N, g0, be0, sc0, sh0);
    bnrelu_kernel<<<(BB * H0N) / 2048, 256>>>(h0h, sc0, sh0, h0t);
    // G3: h1 = h0t @ w1 + b1 (fp16) + fused BN partials
    hgemm_kernel<true, false, true><<<dim3(BB / 128, H1N / 128), 128>>>(
        h0t, w1t, h1h, BB, H1N, H0N, b1, nullptr, ps, psq);
    bn_fin_kernel<<<H1N / 32, 256>>>(ps, psq, H1N, g1, be1, sc1, sh1);
    final_kernel<<<BB / 8, 256>>>(h1h, sc1, sh1, w2, b2, lin, bias, out);
}

// round 14
// speedup vs baseline: 3.4235x; 1.0326x over previous
#include <cuda_runtime.h>
#include <cuda_fp16.h>
#include <math.h>
#include <stdint.h>

#define BB   4096
#define FF   24
#define VV   1000
#define DD   32
#define FD   768
#define COMB 1536
#define H0N  1024
#define H1N  512
#define RED  8
#define EPSV 1e-5f
#define RCH  32            // row chunks for BN partials (BB/128)

// prep mega-kernel block ranges (all 256-thread blocks)
#define GB_GATHER 4096
#define GB_TRW    (FD * FD / 256)                 // 2304
#define GB_W0     ((COMB / 32) * (H0N / 32))      // 1536
#define GB_W1     ((H0N / 32) * (H1N / 32))       // 512
#define GB_TOTAL  (GB_GATHER + GB_TRW + GB_W0 + GB_W1)

// ---------------- device scratch ----------------
__device__ __align__(16) __half g_E2h[2 * BB * FD];
__device__ __align__(16) __half g_WTn[FD * FD];
__device__ __align__(16) __half g_comb[BB * COMB];
__device__ __align__(16) __half g_h0h[BB * H0N];
__device__ __align__(16) __half g_h0t[BB * H0N];
__device__ __align__(16) __half g_h1h[BB * H1N];
__device__ __align__(16) __half g_w0t[H0N * COMB];
__device__ __align__(16) __half g_w1t[H1N * H0N];
__device__ float g_lin[BB];
__device__ __align__(16) float g_ps[RCH * H0N];   // BN partial sums
__device__ __align__(16) float g_psq[RCH * H0N];  // BN partial sumsq

__device__ __forceinline__ void cp16(unsigned dst, const void* src) {
    asm volatile("cp.async.cg.shared.global [%0], [%1], 16;" :: "r"(dst), "l"(src));
}

// ---------------- mega prep kernel -----------------------------------------
__global__ void __launch_bounds__(256)
prep_kernel(const int* __restrict__ x,
            const float* __restrict__ emb,
            const float* __restrict__ lint,
            const float* __restrict__ sw1,
            const float* __restrict__ sw2,
            const float* __restrict__ W,
            const float* __restrict__ w0,
            const float* __restrict__ w1,
            __half* __restrict__ E2h,
            __half* __restrict__ WTn,
            __half* __restrict__ w0t,
            __half* __restrict__ w1t,
            float* __restrict__ linout) {
    __shared__ union {
        float tile[32][33];
        struct {
            int   xs[FF];
            float es[FD];
            float Zs[FF], hid[RED], As[FF], linp[FF];
        } g;
    } sm;

    int blk = blockIdx.x;
    int t = threadIdx.x;

    if (blk < GB_GATHER) {
        int b = blk;
        if (t < FF) sm.g.xs[t] = x[b * FF + t];
        __syncthreads();

        #pragma unroll
        for (int r = 0; r < 3; r++) {
            int ik = t + r * 256;
            int f = ik >> 5, d = ik & 31;
            sm.g.es[ik] = emb[((long)f * VV + sm.g.xs[f]) * DD + d];
        }
        if (t < FF) sm.g.linp[t] = lint[(long)t * VV + sm.g.xs[t]];
        __syncthreads();

        int w = t >> 5, lane = t & 31;
        #pragma unroll
        for (int ff = 0; ff < 3; ff++) {
            int f = w * 3 + ff;
            float v = sm.g.es[f * 32 + lane];
            #pragma unroll
            for (int o = 16; o > 0; o >>= 1) v += __shfl_xor_sync(0xffffffffu, v, o);
            if (lane == 0) sm.g.Zs[f] = v * (1.f / 32.f);
        }
        __syncthreads();
        if (t < RED) {
            float s = 0.f;
            #pragma unroll
            for (int f = 0; f < FF; f++) s += sm.g.Zs[f] * sw1[t * FF + f];
            sm.g.hid[t] = fmaxf(s, 0.f);
        }
        __syncthreads();
        if (t < FF) {
            float s = 0.f;
            #pragma unroll
            for (int r = 0; r < RED; r++) s += sm.g.hid[r] * sw2[t * RED + r];
            sm.g.As[t] = 1.f / (1.f + expf(-s));
        }
        if (t == 0) {
            float s = 0.f;
            #pragma unroll
            for (int f = 0; f < FF; f++) s += sm.g.linp[f];
            linout[b] = s;
        }
        __syncthreads();

        #pragma unroll
        for (int r = 0; r < 3; r++) {
            int ik = t + r * 256;
            int f = ik >> 5;
            float e = sm.g.es[ik];
            E2h[(long)b * FD + ik] = __float2half_rn(e);
            E2h[(long)(BB + b) * FD + ik] = __float2half_rn(sm.g.As[f] * e);
        }
    } else if (blk < GB_GATHER + GB_TRW) {
        int o = (blk - GB_GATHER) * 256 + t;
        int jl = o % FD, ik = o / FD;
        int i = ik >> 5, k = ik & 31, j = jl >> 5, l = jl & 31;
        float v = (i == j) ? 0.f : W[(((i * FF + j) * DD + k) * DD) + l];
        WTn[o] = __float2half_rn(v);
    } else {
        const float* src;
        __half* dst;
        int K, N, kblk, nblk;
        if (blk < GB_GATHER + GB_TRW + GB_W0) {
            int idx = blk - (GB_GATHER + GB_TRW);
            src = w0; dst = w0t; K = COMB; N = H0N;
            kblk = idx % (COMB / 32); nblk = idx / (COMB / 32);
        } else {
            int idx = blk - (GB_GATHER + GB_TRW + GB_W0);
            src = w1; dst = w1t; K = H0N; N = H1N;
            kblk = idx % (H0N / 32); nblk = idx / (H0N / 32);
        }
        int k0 = kblk * 32, n0 = nblk * 32;
        int tx = t & 31, ty = t >> 5;
        #pragma unroll
        for (int j = 0; j < 4; j++)
            sm.tile[ty + j * 8][tx] = src[(long)(k0 + ty + j * 8) * N + n0 + tx];
        __syncthreads();
        #pragma unroll
        for (int j = 0; j < 4; j++)
            dst[(long)(n0 + ty + j * 8) * K + k0 + tx] =
                __float2half_rn(sm.tile[tx][ty + j * 8]);
    }
}

// ---------------- fp16 GEMM: ldmatrix + m16n8k16 + cp.async 4-stage --------
// BNPART: epilogue also emits per-block column sum/sumsq partials
// (chunk = blockIdx.x) into ps/psq.
template <bool BIAS, bool COMBINE, bool BNPART>
__global__ void __launch_bounds__(128, 2)
hgemm_kernel(const __half* __restrict__ A, const __half* __restrict__ Bt,
             __half* __restrict__ C, int M, int N, int K,
             const float* __restrict__ bias, const __half* __restrict__ E2,
             float* __restrict__ ps, float* __restrict__ psq) {
    __shared__ __align__(16) __half Asm[4][2048];
    __shared__ __align__(16) __half Bsm[4][2048];
    __shared__ float bred_s[4][64], bred_q[4][64];
    int t = threadIdx.x;
    int m0 = blockIdx.x * 128, n0 = blockIdx.y * 128;
    int wid = t >> 5, lane = t & 31;
    int wm = (wid & 1) * 64, wn = (wid >> 1) * 64;
    int r = lane >> 2, quad = lane & 3;

    float acc[4][8][4];
    #pragma unroll
    for (int mi = 0; mi < 4; mi++)
        #pragma unroll
        for (int ni = 0; ni < 8; ni++)
            #pragma unroll
            for (int c = 0; c < 4; c++) acc[mi][ni][c] = 0.f;

    int srow = t >> 1, sc = t & 1;
    const __half* Ap = A + (long)(m0 + srow) * K + sc * 8;
    const __half* Bp = Bt + (long)(n0 + srow) * K + sc * 8;
    int swz = (srow >> 2) & 1;
    unsigned off0 = (unsigned)(srow * 16 + ((sc ^ swz) << 3)) * 2u;
    unsigned off1 = (unsigned)((srow + 64) * 16 + ((sc ^ swz) << 3)) * 2u;

    unsigned abase = (unsigned)__cvta_generic_to_shared(Asm[0]);
    unsigned bbase = (unsigned)__cvta_generic_to_shared(Bsm[0]);

    unsigned aaddr[4], baddr[4];
    #pragma unroll
    for (int mi = 0; mi < 4; mi++) {
        int row = wm + mi * 16 + (lane & 7) + ((lane >> 3) & 1) * 8;
        int kc  = (lane >> 4) & 1;
        aaddr[mi] = abase + (unsigned)(row * 16 + ((kc ^ ((row >> 2) & 1)) << 3)) * 2u;
    }
    #pragma unroll
    for (int np = 0; np < 4; np++) {
        int row = wn + np * 16 + (lane & 7) + ((lane >> 4) & 1) * 8;
        int kc  = (lane >> 3) & 1;
        baddr[np] = bbase + (unsigned)(row * 16 + ((kc ^ ((row >> 2) & 1)) << 3)) * 2u;
    }

    int nt = K >> 4;
    long rstep = 64 * (long)K;

    #define STAGE(i)                                                        \
        do {                                                                \
            if ((i) < nt) {                                                 \
                unsigned bo = (unsigned)((i) & 3) * 4096u;                  \
                const __half* ak = Ap + (i) * 16;                           \
                const __half* bk = Bp + (i) * 16;                           \
                cp16(abase + bo + off0, ak);                                \
                cp16(abase + bo + off1, ak + rstep);                        \
                cp16(bbase + bo + off0, bk);                                \
                cp16(bbase + bo + off1, bk + rstep);                        \
            }                                                               \
            asm volatile("cp.async.commit_group;");                         \
        } while (0)

    STAGE(0); STAGE(1); STAGE(2);

    for (int i = 0; i < nt; i++) {
        asm volatile("cp.async.wait_group 2;");
        __syncthreads();
        unsigned boff = (unsigned)(i & 3) * 4096u;
        unsigned af[4][4], bf[4][4];
        #pragma unroll
        for (int mi = 0; mi < 4; mi++)
            asm volatile("ldmatrix.sync.aligned.m8n8.x4.shared.b16 {%0,%1,%2,%3}, [%4];"
                : "=r"(af[mi][0]), "=r"(af[mi][1]), "=r"(af[mi][2]), "=r"(af[mi][3])
                : "r"(aaddr[mi] + boff));
        #pragma unroll
        for (int np = 0; np < 4; np++)
            asm volatile("ldmatrix.sync.aligned.m8n8.x4.shared.b16 {%0,%1,%2,%3}, [%4];"
                : "=r"(bf[np][0]), "=r"(bf[np][1]), "=r"(bf[np][2]), "=r"(bf[np][3])
                : "r"(baddr[np] + boff));
        #pragma unroll
        for (int mi = 0; mi < 4; mi++)
            #pragma unroll
            for (int ni = 0; ni < 8; ni++) {
                asm volatile(
                    "mma.sync.aligned.m16n8k16.row.col.f32.f16.f16.f32 "
                    "{%0,%1,%2,%3}, {%4,%5,%6,%7}, {%8,%9}, {%0,%1,%2,%3};"
                    : "+f"(acc[mi][ni][0]), "+f"(acc[mi][ni][1]),
                      "+f"(acc[mi][ni][2]), "+f"(acc[mi][ni][3])
                    : "r"(af[mi][0]), "r"(af[mi][1]), "r"(af[mi][2]), "r"(af[mi][3]),
                      "r"(bf[ni >> 1][(ni & 1) * 2]), "r"(bf[ni >> 1][(ni & 1) * 2 + 1]));
            }
        STAGE(i + 3);
    }
    #undef STAGE
    asm volatile("cp.async.wait_group 0;");

    float cs[8][2], cq[8][2];
    if (BNPART) {
        #pragma unroll
        for (int ni = 0; ni < 8; ni++) {
            cs[ni][0] = cs[ni][1] = 0.f;
            cq[ni][0] = cq[ni][1] = 0.f;
        }
    }

    #pragma unroll
    for (int mi = 0; mi < 4; mi++) {
        #pragma unroll
        for (int ni = 0; ni < 8; ni++) {
            int row0 = m0 + wm + mi * 16 + r;
            int row1 = row0 + 8;
            int col  = n0 + wn + ni * 8 + 2 * quad;
            float2 v0 = make_float2(acc[mi][ni][0], acc[mi][ni][1]);
            float2 v1 = make_float2(acc[mi][ni][2], acc[mi][ni][3]);
            if (BIAS) {
                float b0v = bias[col], b1v = bias[col + 1];
                v0.x += b0v; v0.y += b1v;
                v1.x += b0v; v1.y += b1v;
            }
            if (COMBINE) {
                float2 e0 = __half22float2(*(const __half2*)&E2[(long)row0 * FD + col]);
                float2 e1 = __half22float2(*(const __half2*)&E2[(long)row1 * FD + col]);
                v0.x *= e0.x; v0.y *= e0.y;
                v1.x *= e1.x; v1.y *= e1.y;
                long br0 = (row0 < BB) ? row0 : (row0 - BB);
                long br1 = (row1 < BB) ? row1 : (row1 - BB);
                int  c0  = (row0 < BB) ? 0 : FD;
                int  c1  = (row1 < BB) ? 0 : FD;
                *(__half2*)&C[br0 * (long)COMB + c0 + col] = __floats2half2_rn(v0.x, v0.y);
                *(__half2*)&C[br1 * (long)COMB + c1 + col] = __floats2half2_rn(v1.x, v1.y);
            } else {
                __half2 h0 = __floats2half2_rn(v0.x, v0.y);
                __half2 h1 = __floats2half2_rn(v1.x, v1.y);
                *(__half2*)&C[(long)row0 * N + col] = h0;
                *(__half2*)&C[(long)row1 * N + col] = h1;
                if (BNPART) {
                    float2 f0 = __half22float2(h0), f1 = __half22float2(h1);
                    cs[ni][0] += f0.x + f1.x;
                    cs[ni][1] += f0.y + f1.y;
                    cq[ni][0] += f0.x * f0.x + f1.x * f1.x;
                    cq[ni][1] += f0.y * f0.y + f1.y * f1.y;
                }
            }
        }
    }

    if (BNPART) {
        #pragma unroll
        for (int ni = 0; ni < 8; ni++)
            #pragma unroll
            for (int j = 0; j < 2; j++) {
                #pragma unroll
                for (int d = 4; d <= 16; d <<= 1) {
                    cs[ni][j] += __shfl_xor_sync(0xffffffffu, cs[ni][j], d);
                    cq[ni][j] += __shfl_xor_sync(0xffffffffu, cq[ni][j], d);
                }
            }
        if (lane < 4) {
            #pragma unroll
            for (int ni = 0; ni < 8; ni++) {
                bred_s[wid][ni * 8 + 2 * lane + 0] = cs[ni][0];
                bred_s[wid][ni * 8 + 2 * lane + 1] = cs[ni][1];
                bred_q[wid][ni * 8 + 2 * lane + 0] = cq[ni][0];
                bred_q[wid][ni * 8 + 2 * lane + 1] = cq[ni][1];
            }
        }
        __syncthreads();
        if ((wid & 1) == 0) {
            int base = n0 + (wid >> 1) * 64;
            #pragma unroll
            for (int c = lane; c < 64; c += 32) {
                float s = bred_s[wid][c] + bred_s[wid | 1][c];
                float q = bred_q[wid][c] + bred_q[wid | 1][c];
                ps[(long)blockIdx.x * N + base + c]  = s;
                psq[(long)blockIdx.x * N + base + c] = q;
            }
        }
    }
}

// ---------------- fused BN finalize + ReLU apply (h0 path) -----------------
// grid (H0N/64, RCH); block 256. Per block: reduce 32 partials for 64 cols
// (4 groups x 8), compute scale/shift in smem, apply to 128x64 tile.
__global__ void __launch_bounds__(256)
bnfin_relu_kernel(const float* __restrict__ ps, const float* __restrict__ psq,
                  const float* __restrict__ g, const float* __restrict__ be,
                  const __half* __restrict__ H, __half* __restrict__ Ht) {
    __shared__ float red_s[4][64], red_q[4][64];
    __shared__ float sc_s[64], sc_h[64];
    int t = threadIdx.x;
    int c64 = t & 63, grp = t >> 6;                // 4 groups of 8 chunks
    int col = blockIdx.x * 64 + c64;
    float s = 0.f, q = 0.f;
    #pragma unroll
    for (int i = 0; i < 8; i++) {
        long o = (long)(grp * 8 + i) * H0N + col;
        s += ps[o]; q += psq[o];
    }
    red_s[grp][c64] = s; red_q[grp][c64] = q;
    __syncthreads();
    if (grp == 0) {
        #pragma unroll
        for (int i = 1; i < 4; i++) { s += red_s[i][c64]; q += red_q[i][c64]; }
        float mean = s * (1.f / BB);
        float var  = q * (1.f / BB) - mean * mean;
        float sc   = g[col] * rsqrtf(var + EPSV);
        sc_s[c64] = sc;
        sc_h[c64] = be[col] - mean * sc;
    }
    __syncthreads();
    // apply: rows blockIdx.y*128..+127, cols blockIdx.x*64..+63
    int w = t >> 5, lane = t & 31;                 // warp = one row segment
    int lc = lane * 2;
    float a_sc0 = sc_s[lc], a_sh0 = sc_h[lc];
    float a_sc1 = sc_s[lc + 1], a_sh1 = sc_h[lc + 1];
    #pragma unroll 4
    for (int it = 0; it < 16; it++) {
        int row = blockIdx.y * 128 + it * 8 + w;
        long idx = (long)row * H0N + blockIdx.x * 64 + lc;
        float2 v = __half22float2(*(const __half2*)&H[idx]);
        float a = fmaxf(0.f, v.x * a_sc0 + a_sh0);
        float b = fmaxf(0.f, v.y * a_sc1 + a_sh1);
        *(__half2*)&Ht[idx] = __floats2half2_rn(a, b);
    }
}

// ---------------- fused BN1 finalize + final dot + sigmoid -----------------
// grid 64; block 256 (8 warps x 8 rows each). Phase 1: all 512 scale/shift
// from partials (dup across blocks, L2-resident). Phase 2: dot w2 + sigmoid.
__global__ void __launch_bounds__(256)
final_kernel(const float* __restrict__ ps, const float* __restrict__ psq,
             const float* __restrict__ g, const float* __restrict__ be,
             const __half* __restrict__ H1,
             const float* __restrict__ w2, const float* __restrict__ b2,
             const float* __restrict__ lin, const float* __restrict__ bias0,
             float* __restrict__ out) {
    __shared__ float sc_s[H1N], sc_h[H1N];
    int t = threadIdx.x;
    #pragma unroll
    for (int h = 0; h < 2; h++) {
        int col = t + h * 256;
        float s = 0.f, q = 0.f;
        #pragma unroll
        for (int i = 0; i < RCH; i++) {
            long o = (long)i * H1N + col;
            s += ps[o]; q += psq[o];
        }
        float mean = s * (1.f / BB);
        float var  = q * (1.f / BB) - mean * mean;
        float sc   = g[col] * rsqrtf(var + EPSV);
        sc_s[col] = sc;
        sc_h[col] = be[col] - mean * sc;
    }
    __syncthreads();

    int warp = t >> 5, lane = t & 31;
    #pragma unroll
    for (int rr = 0; rr < 8; rr++) {
        int row = blockIdx.x * 64 + warp * 8 + rr;
        float acc = 0.f;
        #pragma unroll
        for (int k = lane * 2; k < H1N; k += 64) {
            float2 v = __half22float2(*(const __half2*)&H1[(long)row * H1N + k]);
            float a = fmaxf(0.f, v.x * sc_s[k] + sc_h[k]);
            float b = fmaxf(0.f, v.y * sc_s[k + 1] + sc_h[k + 1]);
            acc += a * w2[k] + b * w2[k + 1];
        }
        #pragma unroll
        for (int o = 16; o > 0; o >>= 1) acc += __shfl_xor_sync(0xffffffffu, acc, o);
        if (lane == 0) {
            float logit = acc + b2[0] + lin[row] + bias0[0];
            out[row] = 1.f / (1.f + expf(-logit));
        }
    }
}

// ---------------------------------------------------------------------------
extern "C" void kernel_launch(void* const* d_in, const int* in_sizes, int n_in,
                              void* d_out, int out_size) {
    const int*   x    = (const int*)d_in[0];
    const float* emb  = (const float*)d_in[1];
    const float* lint = (const float*)d_in[2];
    const float* bias = (const float*)d_in[3];
    const float* sw1  = (const float*)d_in[4];
    const float* sw2  = (const float*)d_in[5];
    const float* bilW = (const float*)d_in[6];
    const float* w0   = (const float*)d_in[7];
    const float* b0   = (const float*)d_in[8];
    const float* g0   = (const float*)d_in[9];
    const float* be0  = (const float*)d_in[10];
    const float* w1   = (const float*)d_in[11];
    const float* b1   = (const float*)d_in[12];
    const float* g1   = (const float*)d_in[13];
    const float* be1  = (const float*)d_in[14];
    const float* w2   = (const float*)d_in[15];
    const float* b2   = (const float*)d_in[16];
    float* out = (float*)d_out;

    __half *E2h, *WTn, *comb, *h0h, *h0t, *h1h, *w0t, *w1t;
    float *lin, *ps, *psq;
    cudaGetSymbolAddress((void**)&E2h,  g_E2h);
    cudaGetSymbolAddress((void**)&WTn,  g_WTn);
    cudaGetSymbolAddress((void**)&comb, g_comb);
    cudaGetSymbolAddress((void**)&h0h,  g_h0h);
    cudaGetSymbolAddress((void**)&h0t,  g_h0t);
    cudaGetSymbolAddress((void**)&h1h,  g_h1h);
    cudaGetSymbolAddress((void**)&w0t,  g_w0t);
    cudaGetSymbolAddress((void**)&w1t,  g_w1t);
    cudaGetSymbolAddress((void**)&lin,  g_lin);
    cudaGetSymbolAddress((void**)&ps,   g_ps);
    cudaGetSymbolAddress((void**)&psq,  g_psq);

    // P: all independent producers in one launch (gather blocks first)
    prep_kernel<<<GB_TOTAL, 256>>>(x, emb, lint, sw1, sw2, bilW, w0, w1,
                                   E2h, WTn, w0t, w1t, lin);
    // G1: comb = (E2 @ WTn^T) * E2 -> [p|q] scatter (fp16)
    hgemm_kernel<false, true, false><<<dim3(2 * BB / 128, FD / 128), 128>>>(
        E2h, WTn, comb, 2 * BB, FD, FD, nullptr, E2h, nullptr, nullptr);
    // G2: h0 = comb @ w0 + b0 (fp16) + fused BN partials
    hgemm_kernel<true, false, true><<<dim3(BB / 128, H0N / 128), 128>>>(
        comb, w0t, h0h, BB, H0N, COMB, b0, nullptr, ps, psq);
    // fused BN0 finalize + ReLU apply
    bnfin_relu_kernel<<<dim3(H0N / 64, RCH), 256>>>(ps, psq, g0, be0, h0h, h0t);
    // G3: h1 = h0t @ w1 + b1 (fp16) + fused BN partials
    hgemm_kernel<true, false, true><<<dim3(BB / 128, H1N / 128), 128>>>(
        h0t, w1t, h1h, BB, H1N, H0N, b1, nullptr, ps, psq);
    // fused BN1 finalize + final dot + sigmoid
    final_kernel<<<BB / 64, 256>>>(ps, psq, g1, be1, h1h, w2, b2, lin, bias, out);
}

// round 15
// speedup vs baseline: 3.4865x; 1.0184x over previous
#include <cuda_runtime.h>
#include <cuda_fp16.h>
#include <math.h>
#include <stdint.h>

#define BB   4096
#define FF   24
#define VV   1000
#define DD   32
#define FD   768
#define COMB 1536
#define H0N  1024
#define H1N  512
#define RED  8
#define EPSV 1e-5f
#define RCH  32            // row chunks for BN partials (BB/128)

// prep mega-kernel block ranges (all 256-thread blocks)
#define GB_GATHER 4096
#define GB_TRW    (FD * FD / 256)                 // 2304
#define GB_W0     ((COMB / 32) * (H0N / 32))      // 1536
#define GB_W1     ((H0N / 32) * (H1N / 32))       // 512
#define GB_TOTAL  (GB_GATHER + GB_TRW + GB_W0 + GB_W1)

// ---------------- device scratch ----------------
__device__ __align__(16) __half g_E2h[2 * BB * FD];
__device__ __align__(16) __half g_WTn[FD * FD];
__device__ __align__(16) __half g_comb[BB * COMB];
__device__ __align__(16) __half g_h0h[BB * H0N];
__device__ __align__(16) __half g_h0t[BB * H0N];
__device__ __align__(16) __half g_h1h[BB * H1N];
__device__ __align__(16) __half g_w0t[H0N * COMB];
__device__ __align__(16) __half g_w1t[H1N * H0N];
__device__ float g_lin[BB];
__device__ __align__(16) float g_ps[RCH * H0N];   // BN partial sums
__device__ __align__(16) float g_psq[RCH * H0N];  // BN partial sumsq

__device__ __forceinline__ void cp16(unsigned dst, const void* src) {
    asm volatile("cp.async.cg.shared.global [%0], [%1], 16;" :: "r"(dst), "l"(src));
}

// ---------------- mega prep kernel -----------------------------------------
__global__ void __launch_bounds__(256)
prep_kernel(const int* __restrict__ x,
            const float* __restrict__ emb,
            const float* __restrict__ lint,
            const float* __restrict__ sw1,
            const float* __restrict__ sw2,
            const float* __restrict__ W,
            const float* __restrict__ w0,
            const float* __restrict__ w1,
            __half* __restrict__ E2h,
            __half* __restrict__ WTn,
            __half* __restrict__ w0t,
            __half* __restrict__ w1t,
            float* __restrict__ linout) {
    __shared__ union {
        float tile[32][33];
        struct {
            int   xs[FF];
            float es[FD];
            float Zs[FF], hid[RED], As[FF], linp[FF];
        } g;
    } sm;

    int blk = blockIdx.x;
    int t = threadIdx.x;

    if (blk < GB_GATHER) {
        int b = blk;
        if (t < FF) sm.g.xs[t] = x[b * FF + t];
        __syncthreads();

        #pragma unroll
        for (int r = 0; r < 3; r++) {
            int ik = t + r * 256;
            int f = ik >> 5, d = ik & 31;
            sm.g.es[ik] = emb[((long)f * VV + sm.g.xs[f]) * DD + d];
        }
        if (t < FF) sm.g.linp[t] = lint[(long)t * VV + sm.g.xs[t]];
        __syncthreads();

        int w = t >> 5, lane = t & 31;
        #pragma unroll
        for (int ff = 0; ff < 3; ff++) {
            int f = w * 3 + ff;
            float v = sm.g.es[f * 32 + lane];
            #pragma unroll
            for (int o = 16; o > 0; o >>= 1) v += __shfl_xor_sync(0xffffffffu, v, o);
            if (lane == 0) sm.g.Zs[f] = v * (1.f / 32.f);
        }
        __syncthreads();
        if (t < RED) {
            float s = 0.f;
            #pragma unroll
            for (int f = 0; f < FF; f++) s += sm.g.Zs[f] * sw1[t * FF + f];
            sm.g.hid[t] = fmaxf(s, 0.f);
        }
        __syncthreads();
        if (t < FF) {
            float s = 0.f;
            #pragma unroll
            for (int r = 0; r < RED; r++) s += sm.g.hid[r] * sw2[t * RED + r];
            sm.g.As[t] = 1.f / (1.f + expf(-s));
        }
        if (t == 0) {
            float s = 0.f;
            #pragma unroll
            for (int f = 0; f < FF; f++) s += sm.g.linp[f];
            linout[b] = s;
        }
        __syncthreads();

        #pragma unroll
        for (int r = 0; r < 3; r++) {
            int ik = t + r * 256;
            int f = ik >> 5;
            float e = sm.g.es[ik];
            E2h[(long)b * FD + ik] = __float2half_rn(e);
            E2h[(long)(BB + b) * FD + ik] = __float2half_rn(sm.g.As[f] * e);
        }
    } else if (blk < GB_GATHER + GB_TRW) {
        int o = (blk - GB_GATHER) * 256 + t;
        int jl = o % FD, ik = o / FD;
        int i = ik >> 5, k = ik & 31, j = jl >> 5, l = jl & 31;
        float v = (i == j) ? 0.f : W[(((i * FF + j) * DD + k) * DD) + l];
        WTn[o] = __float2half_rn(v);
    } else {
        const float* src;
        __half* dst;
        int K, N, kblk, nblk;
        if (blk < GB_GATHER + GB_TRW + GB_W0) {
            int idx = blk - (GB_GATHER + GB_TRW);
            src = w0; dst = w0t; K = COMB; N = H0N;
            kblk = idx % (COMB / 32); nblk = idx / (COMB / 32);
        } else {
            int idx = blk - (GB_GATHER + GB_TRW + GB_W0);
            src = w1; dst = w1t; K = H0N; N = H1N;
            kblk = idx % (H0N / 32); nblk = idx / (H0N / 32);
        }
        int k0 = kblk * 32, n0 = nblk * 32;
        int tx = t & 31, ty = t >> 5;
        #pragma unroll
        for (int j = 0; j < 4; j++)
            sm.tile[ty + j * 8][tx] = src[(long)(k0 + ty + j * 8) * N + n0 + tx];
        __syncthreads();
        #pragma unroll
        for (int j = 0; j < 4; j++)
            dst[(long)(n0 + ty + j * 8) * K + k0 + tx] =
                __float2half_rn(sm.tile[tx][ty + j * 8]);
    }
}

// ---------------- fp16 GEMM: ldmatrix + m16n8k16 + cp.async 4-stage --------
// BNPART: epilogue also emits per-block column sum/sumsq partials
// (chunk = blockIdx.x) into ps/psq.
template <bool BIAS, bool COMBINE, bool BNPART>
__global__ void __launch_bounds__(128, 2)
hgemm_kernel(const __half* __restrict__ A, const __half* __restrict__ Bt,
             __half* __restrict__ C, int M, int N, int K,
             const float* __restrict__ bias, const __half* __restrict__ E2,
             float* __restrict__ ps, float* __restrict__ psq) {
    __shared__ __align__(16) __half Asm[4][2048];
    __shared__ __align__(16) __half Bsm[4][2048];
    __shared__ float bred_s[4][64], bred_q[4][64];
    int t = threadIdx.x;
    int m0 = blockIdx.x * 128, n0 = blockIdx.y * 128;
    int wid = t >> 5, lane = t & 31;
    int wm = (wid & 1) * 64, wn = (wid >> 1) * 64;
    int r = lane >> 2, quad = lane & 3;

    float acc[4][8][4];
    #pragma unroll
    for (int mi = 0; mi < 4; mi++)
        #pragma unroll
        for (int ni = 0; ni < 8; ni++)
            #pragma unroll
            for (int c = 0; c < 4; c++) acc[mi][ni][c] = 0.f;

    int srow = t >> 1, sc = t & 1;
    const __half* Ap = A + (long)(m0 + srow) * K + sc * 8;
    const __half* Bp = Bt + (long)(n0 + srow) * K + sc * 8;
    int swz = (srow >> 2) & 1;
    unsigned off0 = (unsigned)(srow * 16 + ((sc ^ swz) << 3)) * 2u;
    unsigned off1 = (unsigned)((srow + 64) * 16 + ((sc ^ swz) << 3)) * 2u;

    unsigned abase = (unsigned)__cvta_generic_to_shared(Asm[0]);
    unsigned bbase = (unsigned)__cvta_generic_to_shared(Bsm[0]);

    unsigned aaddr[4], baddr[4];
    #pragma unroll
    for (int mi = 0; mi < 4; mi++) {
        int row = wm + mi * 16 + (lane & 7) + ((lane >> 3) & 1) * 8;
        int kc  = (lane >> 4) & 1;
        aaddr[mi] = abase + (unsigned)(row * 16 + ((kc ^ ((row >> 2) & 1)) << 3)) * 2u;
    }
    #pragma unroll
    for (int np = 0; np < 4; np++) {
        int row = wn + np * 16 + (lane & 7) + ((lane >> 4) & 1) * 8;
        int kc  = (lane >> 3) & 1;
        baddr[np] = bbase + (unsigned)(row * 16 + ((kc ^ ((row >> 2) & 1)) << 3)) * 2u;
    }

    int nt = K >> 4;
    long rstep = 64 * (long)K;

    #define STAGE(i)                                                        \
        do {                                                                \
            if ((i) < nt) {                                                 \
                unsigned bo = (unsigned)((i) & 3) * 4096u;                  \
                const __half* ak = Ap + (i) * 16;                           \
                const __half* bk = Bp + (i) * 16;                           \
                cp16(abase + bo + off0, ak);                                \
                cp16(abase + bo + off1, ak + rstep);                        \
                cp16(bbase + bo + off0, bk);                                \
                cp16(bbase + bo + off1, bk + rstep);                        \
            }                                                               \
            asm volatile("cp.async.commit_group;");                         \
        } while (0)

    STAGE(0); STAGE(1); STAGE(2);

    for (int i = 0; i < nt; i++) {
        asm volatile("cp.async.wait_group 2;");
        __syncthreads();
        unsigned boff = (unsigned)(i & 3) * 4096u;
        unsigned af[4][4], bf[4][4];
        #pragma unroll
        for (int mi = 0; mi < 4; mi++)
            asm volatile("ldmatrix.sync.aligned.m8n8.x4.shared.b16 {%0,%1,%2,%3}, [%4];"
                : "=r"(af[mi][0]), "=r"(af[mi][1]), "=r"(af[mi][2]), "=r"(af[mi][3])
                : "r"(aaddr[mi] + boff));
        #pragma unroll
        for (int np = 0; np < 4; np++)
            asm volatile("ldmatrix.sync.aligned.m8n8.x4.shared.b16 {%0,%1,%2,%3}, [%4];"
                : "=r"(bf[np][0]), "=r"(bf[np][1]), "=r"(bf[np][2]), "=r"(bf[np][3])
                : "r"(baddr[np] + boff));
        #pragma unroll
        for (int mi = 0; mi < 4; mi++)
            #pragma unroll
            for (int ni = 0; ni < 8; ni++) {
                asm volatile(
                    "mma.sync.aligned.m16n8k16.row.col.f32.f16.f16.f32 "
                    "{%0,%1,%2,%3}, {%4,%5,%6,%7}, {%8,%9}, {%0,%1,%2,%3};"
                    : "+f"(acc[mi][ni][0]), "+f"(acc[mi][ni][1]),
                      "+f"(acc[mi][ni][2]), "+f"(acc[mi][ni][3])
                    : "r"(af[mi][0]), "r"(af[mi][1]), "r"(af[mi][2]), "r"(af[mi][3]),
                      "r"(bf[ni >> 1][(ni & 1) * 2]), "r"(bf[ni >> 1][(ni & 1) * 2 + 1]));
            }
        STAGE(i + 3);
    }
    #undef STAGE
    asm volatile("cp.async.wait_group 0;");

    float cs[8][2], cq[8][2];
    if (BNPART) {
        #pragma unroll
        for (int ni = 0; ni < 8; ni++) {
            cs[ni][0] = cs[ni][1] = 0.f;
            cq[ni][0] = cq[ni][1] = 0.f;
        }
    }

    #pragma unroll
    for (int mi = 0; mi < 4; mi++) {
        #pragma unroll
        for (int ni = 0; ni < 8; ni++) {
            int row0 = m0 + wm + mi * 16 + r;
            int row1 = row0 + 8;
            int col  = n0 + wn + ni * 8 + 2 * quad;
            float2 v0 = make_float2(acc[mi][ni][0], acc[mi][ni][1]);
            float2 v1 = make_float2(acc[mi][ni][2], acc[mi][ni][3]);
            if (BIAS) {
                float b0v = bias[col], b1v = bias[col + 1];
                v0.x += b0v; v0.y += b1v;
                v1.x += b0v; v1.y += b1v;
            }
            if (COMBINE) {
                float2 e0 = __half22float2(*(const __half2*)&E2[(long)row0 * FD + col]);
                float2 e1 = __half22float2(*(const __half2*)&E2[(long)row1 * FD + col]);
                v0.x *= e0.x; v0.y *= e0.y;
                v1.x *= e1.x; v1.y *= e1.y;
                long br0 = (row0 < BB) ? row0 : (row0 - BB);
                long br1 = (row1 < BB) ? row1 : (row1 - BB);
                int  c0  = (row0 < BB) ? 0 : FD;
                int  c1  = (row1 < BB) ? 0 : FD;
                *(__half2*)&C[br0 * (long)COMB + c0 + col] = __floats2half2_rn(v0.x, v0.y);
                *(__half2*)&C[br1 * (long)COMB + c1 + col] = __floats2half2_rn(v1.x, v1.y);
            } else {
                __half2 h0 = __floats2half2_rn(v0.x, v0.y);
                __half2 h1 = __floats2half2_rn(v1.x, v1.y);
                *(__half2*)&C[(long)row0 * N + col] = h0;
                *(__half2*)&C[(long)row1 * N + col] = h1;
                if (BNPART) {
                    float2 f0 = __half22float2(h0), f1 = __half22float2(h1);
                    cs[ni][0] += f0.x + f1.x;
                    cs[ni][1] += f0.y + f1.y;
                    cq[ni][0] += f0.x * f0.x + f1.x * f1.x;
                    cq[ni][1] += f0.y * f0.y + f1.y * f1.y;
                }
            }
        }
    }

    if (BNPART) {
        #pragma unroll
        for (int ni = 0; ni < 8; ni++)
            #pragma unroll
            for (int j = 0; j < 2; j++) {
                #pragma unroll
                for (int d = 4; d <= 16; d <<= 1) {
                    cs[ni][j] += __shfl_xor_sync(0xffffffffu, cs[ni][j], d);
                    cq[ni][j] += __shfl_xor_sync(0xffffffffu, cq[ni][j], d);
                }
            }
        if (lane < 4) {
            #pragma unroll
            for (int ni = 0; ni < 8; ni++) {
                bred_s[wid][ni * 8 + 2 * lane + 0] = cs[ni][0];
                bred_s[wid][ni * 8 + 2 * lane + 1] = cs[ni][1];
                bred_q[wid][ni * 8 + 2 * lane + 0] = cq[ni][0];
                bred_q[wid][ni * 8 + 2 * lane + 1] = cq[ni][1];
            }
        }
        __syncthreads();
        if ((wid & 1) == 0) {
            int base = n0 + (wid >> 1) * 64;
            #pragma unroll
            for (int c = lane; c < 64; c += 32) {
                float s = bred_s[wid][c] + bred_s[wid | 1][c];
                float q = bred_q[wid][c] + bred_q[wid | 1][c];
                ps[(long)blockIdx.x * N + base + c]  = s;
                psq[(long)blockIdx.x * N + base + c] = q;
            }
        }
    }
}

// ---------------- fused BN finalize + ReLU apply (h0 path), wide -----------
// grid (H0N/64, RCH); block 256. Reduce 32 partials for 64 cols, then apply
// BN+ReLU to the 128x64 tile with uint4 (8-half) loads/stores.
__global__ void __launch_bounds__(256)
bnfin_relu_kernel(const float* __restrict__ ps, const float* __restrict__ psq,
                  const float* __restrict__ g, const float* __restrict__ be,
                  const __half* __restrict__ H, __half* __restrict__ Ht) {
    __shared__ float red_s[4][64], red_q[4][64];
    __shared__ float sc_s[64], sc_h[64];
    int t = threadIdx.x;
    int c64 = t & 63, grp = t >> 6;                // 4 groups of 8 chunks
    int col = blockIdx.x * 64 + c64;
    float s = 0.f, q = 0.f;
    #pragma unroll
    for (int i = 0; i < 8; i++) {
        long o = (long)(grp * 8 + i) * H0N + col;
        s += ps[o]; q += psq[o];
    }
    red_s[grp][c64] = s; red_q[grp][c64] = q;
    __syncthreads();
    if (grp == 0) {
        #pragma unroll
        for (int i = 1; i < 4; i++) { s += red_s[i][c64]; q += red_q[i][c64]; }
        float mean = s * (1.f / BB);
        float var  = q * (1.f / BB) - mean * mean;
        float sc   = g[col] * rsqrtf(var + EPSV);
        sc_s[c64] = sc;
        sc_h[c64] = be[col] - mean * sc;
    }
    __syncthreads();
    // apply: 8 cols per thread (uint4); 32 rows per iter; 4 iters for 128 rows.
    int c8 = (t & 7) * 8;
    int rw = t >> 3;                               // 0..31
    float scv[8], shv[8];
    #pragma unroll
    for (int j = 0; j < 8; j++) { scv[j] = sc_s[c8 + j]; shv[j] = sc_h[c8 + j]; }
    #pragma unroll
    for (int it = 0; it < 4; it++) {
        int row = blockIdx.y * 128 + it * 32 + rw;
        long idx = (long)row * H0N + blockIdx.x * 64 + c8;
        uint4 raw = *(const uint4*)&H[idx];
        const __half2* hp = (const __half2*)&raw;
        uint4 ow;
        __half2* op = (__half2*)&ow;
        #pragma unroll
        for (int j = 0; j < 4; j++) {
            float2 v = __half22float2(hp[j]);
            float a = fmaxf(0.f, v.x * scv[2 * j] + shv[2 * j]);
            float b = fmaxf(0.f, v.y * scv[2 * j + 1] + shv[2 * j + 1]);
            op[j] = __floats2half2_rn(a, b);
        }
        *(uint4*)&Ht[idx] = ow;
    }
}

// ---------------- fused BN1 finalize + final dot + sigmoid, wide -----------
// grid 64; block 256 (8 warps x 8 rows each). Phase 1: all 512 scale/shift
// + w2 staged into smem. Phase 2: uint4 dot + sigmoid.
__global__ void __launch_bounds__(256)
final_kernel(const float* __restrict__ ps, const float* __restrict__ psq,
             const float* __restrict__ g, const float* __restrict__ be,
             const __half* __restrict__ H1,
             const float* __restrict__ w2, const float* __restrict__ b2,
             const float* __restrict__ lin, const float* __restrict__ bias0,
             float* __restrict__ out) {
    __shared__ float sc_s[H1N], sc_h[H1N], sm_w2[H1N];
    int t = threadIdx.x;
    #pragma unroll
    for (int h = 0; h < 2; h++) {
        int col = t + h * 256;
        float s = 0.f, q = 0.f;
        #pragma unroll
        for (int i = 0; i < RCH; i++) {
            long o = (long)i * H1N + col;
            s += ps[o]; q += psq[o];
        }
        float mean = s * (1.f / BB);
        float var  = q * (1.f / BB) - mean * mean;
        float sc   = g[col] * rsqrtf(var + EPSV);
        sc_s[col] = sc;
        sc_h[col] = be[col] - mean * sc;
        sm_w2[col] = w2[col];
    }
    __syncthreads();

    int warp = t >> 5, lane = t & 31;
    #pragma unroll
    for (int rr = 0; rr < 8; rr++) {
        int row = blockIdx.x * 64 + warp * 8 + rr;
        float acc = 0.f;
        #pragma unroll
        for (int it = 0; it < 2; it++) {
            int k = (lane + it * 32) * 8;
            uint4 raw = *(const uint4*)&H1[(long)row * H1N + k];
            const __half2* hp = (const __half2*)&raw;
            #pragma unroll
            for (int j = 0; j < 4; j++) {
                float2 v = __half22float2(hp[j]);
                int kk = k + 2 * j;
                float a = fmaxf(0.f, v.x * sc_s[kk] + sc_h[kk]);
                float b = fmaxf(0.f, v.y * sc_s[kk + 1] + sc_h[kk + 1]);
                acc += a * sm_w2[kk] + b * sm_w2[kk + 1];
            }
        }
        #pragma unroll
        for (int o = 16; o > 0; o >>= 1) acc += __shfl_xor_sync(0xffffffffu, acc, o);
        if (lane == 0) {
            float logit = acc + b2[0] + lin[row] + bias0[0];
            out[row] = 1.f / (1.f + expf(-logit));
        }
    }
}

// ---------------------------------------------------------------------------
extern "C" void kernel_launch(void* const* d_in, const int* in_sizes, int n_in,
                              void* d_out, int out_size) {
    const int*   x    = (const int*)d_in[0];
    const float* emb  = (const float*)d_in[1];
    const float* lint = (const float*)d_in[2];
    const float* bias = (const float*)d_in[3];
    const float* sw1  = (const float*)d_in[4];
    const float* sw2  = (const float*)d_in[5];
    const float* bilW = (const float*)d_in[6];
    const float* w0   = (const float*)d_in[7];
    const float* b0   = (const float*)d_in[8];
    const float* g0   = (const float*)d_in[9];
    const float* be0  = (const float*)d_in[10];
    const float* w1   = (const float*)d_in[11];
    const float* b1   = (const float*)d_in[12];
    const float* g1   = (const float*)d_in[13];
    const float* be1  = (const float*)d_in[14];
    const float* w2   = (const float*)d_in[15];
    const float* b2   = (const float*)d_in[16];
    float* out = (float*)d_out;

    __half *E2h, *WTn, *comb, *h0h, *h0t, *h1h, *w0t, *w1t;
    float *lin, *ps, *psq;
    cudaGetSymbolAddress((void**)&E2h,  g_E2h);
    cudaGetSymbolAddress((void**)&WTn,  g_WTn);
    cudaGetSymbolAddress((void**)&comb, g_comb);
    cudaGetSymbolAddress((void**)&h0h,  g_h0h);
    cudaGetSymbolAddress((void**)&h0t,  g_h0t);
    cudaGetSymbolAddress((void**)&h1h,  g_h1h);
    cudaGetSymbolAddress((void**)&w0t,  g_w0t);
    cudaGetSymbolAddress((void**)&w1t,  g_w1t);
    cudaGetSymbolAddress((void**)&lin,  g_lin);
    cudaGetSymbolAddress((void**)&ps,   g_ps);
    cudaGetSymbolAddress((void**)&psq,  g_psq);

    // P: all independent producers in one launch (gather blocks first)
    prep_kernel<<<GB_TOTAL, 256>>>(x, emb, lint, sw1, sw2, bilW, w0, w1,
                                   E2h, WTn, w0t, w1t, lin);
    // G1: comb = (E2 @ WTn^T) * E2 -> [p|q] scatter (fp16)
    hgemm_kernel<false, true, false><<<dim3(2 * BB / 128, FD / 128), 128>>>(
        E2h, WTn, comb, 2 * BB, FD, FD, nullptr, E2h, nullptr, nullptr);
    // G2: h0 = comb @ w0 + b0 (fp16) + fused BN partials
    hgemm_kernel<true, false, true><<<dim3(BB / 128, H0N / 128), 128>>>(
        comb, w0t, h0h, BB, H0N, COMB, b0, nullptr, ps, psq);
    // fused BN0 finalize + ReLU apply (wide)
    bnfin_relu_kernel<<<dim3(H0N / 64, RCH), 256>>>(ps, psq, g0, be0, h0h, h0t);
    // G3: h1 = h0t @ w1 + b1 (fp16) + fused BN partials
    hgemm_kernel<true, false, true><<<dim3(BB / 128, H1N / 128), 128>>>(
        h0t, w1t, h1h, BB, H1N, H0N, b1, nullptr, ps, psq);
    // fused BN1 finalize + final dot + sigmoid (wide)
    final_kernel<<<BB / 64, 256>>>(ps, psq, g1, be1, h1h, w2, b2, lin, bias, out);
}